// round 6
// baseline (speedup 1.0000x reference)
#include <cuda_runtime.h>
#include <cuda_bf16.h>
#include <cstdint>

#define LEVELS 18
#define NNODES ((1 << LEVELS) - 1)

// Persisted state + preconverted weights (device globals; no runtime alloc).
__device__ float         g_c   [(size_t)NNODES * 64];  // cell state, cols 0..63 only
__device__ __nv_bfloat16 g_hh  [(size_t)NNODES * 64];  // h bf16 hi, cols 0..63
__device__ __nv_bfloat16 g_hl  [(size_t)NNODES * 64];  // h bf16 lo
__device__ __nv_bfloat16 g_Whi [512 * 192];            // [gate][k] concat(Wih,Whh) hi
__device__ __nv_bfloat16 g_Wlo [512 * 192];            // lo
__device__ float         g_bsum[512];

// ------------------------------------------------------------------ helpers
__device__ __forceinline__ uint32_t smem_u32(const void* p) {
    uint32_t a;
    asm("{ .reg .u64 t; cvta.to.shared.u64 t, %1; cvt.u32.u64 %0, t; }"
        : "=r"(a) : "l"(p));
    return a;
}
__device__ __forceinline__ void ldsm_x4(uint32_t* r, uint32_t addr) {
    asm volatile("ldmatrix.sync.aligned.m8n8.x4.shared.b16 {%0,%1,%2,%3}, [%4];"
                 : "=r"(r[0]), "=r"(r[1]), "=r"(r[2]), "=r"(r[3]) : "r"(addr));
}
__device__ __forceinline__ void mma_bf16(float* d, const uint32_t* a, const uint32_t* b) {
    asm volatile("mma.sync.aligned.m16n8k16.row.col.f32.bf16.bf16.f32 "
                 "{%0,%1,%2,%3}, {%4,%5,%6,%7}, {%8,%9}, {%0,%1,%2,%3};"
                 : "+f"(d[0]), "+f"(d[1]), "+f"(d[2]), "+f"(d[3])
                 : "r"(a[0]), "r"(a[1]), "r"(a[2]), "r"(a[3]), "r"(b[0]), "r"(b[1]));
}
__device__ __forceinline__ void cp_async16(uint32_t saddr, const void* g) {
    asm volatile("cp.async.ca.shared.global [%0], [%1], 16;"
                 :: "r"(saddr), "l"(g) : "memory");
}
__device__ __forceinline__ void cp_async_commit() {
    asm volatile("cp.async.commit_group;" ::: "memory");
}
__device__ __forceinline__ void split2(float v, __nv_bfloat16& hi, __nv_bfloat16& lo) {
    hi = __float2bfloat16(v);
    lo = __float2bfloat16(v - __bfloat162float(hi));
}
__device__ __forceinline__ float sigf(float z) {
    return __fdividef(1.0f, 1.0f + __expf(-z));
}
__device__ __forceinline__ float tanha(float z) {
    return __fdividef(2.0f, 1.0f + __expf(-2.0f * z)) - 1.0f;
}

// ---------------------------------------------------------------- SMEM plan
// Row stride 400B: rows hit distinct bank quads -> conflict-free ldmatrix.
#define RS 400
#define OFF_BIAS 0
#define OFF_AHI  2048
#define OFF_ALO  (OFF_AHI + 128 * RS)   // 53248
#define OFF_B    (OFF_ALO + 128 * RS)   // 104448; buf b: hi at +b*51200, lo +25600
#define BUF_SZ   51200
#define SMEM_TC  (OFF_B + 2 * BUF_SZ)   // 206848 (1 CTA/SM)

// ---------------------------------------------------------------- prep
__global__ void prep_kernel(const float* __restrict__ Wih,
                            const float* __restrict__ Whh,
                            const float* __restrict__ bih,
                            const float* __restrict__ bhh)
{
    int idx = blockIdx.x * blockDim.x + threadIdx.x;
    if (idx < 512) g_bsum[idx] = bih[idx] + bhh[idx];
    for (int p = idx; p < 512 * 192; p += gridDim.x * blockDim.x) {
        int g = p / 192, k = p - g * 192;
        float v = (k < 64) ? Wih[g * 64 + k] : Whh[g * 128 + (k - 64)];
        __nv_bfloat16 hi, lo;
        split2(v, hi, lo);
        g_Whi[p] = hi;
        g_Wlo[p] = lo;
    }
}

// =====================================================================
// Tensor-core level kernel: CTA = 128 nodes x 512 gates, 256 threads,
// 8 warps = 4 row-groups (32 nodes) x 2 chunk-halves (4 j-tiles).
// 8 gate-chunks of 64 (double-buffered cp.async prefetch).
// Chunk tile j (0..7): gate type j&3, hu octet j>>2. Warp cq owns
// j=4cq..4cq+3 = full (i,f,g,o) quad -> register-local epilogue.
// B row rr=8j+p -> gate ((j&3)<<7) + nc*16 + ((j>>2)<<3) + p.
// =====================================================================
__global__ __launch_bounds__(256, 1)
void lstm_tc_kernel(const float* __restrict__ x,
                    float* __restrict__ out,
                    int start, int isLeaf)
{
    extern __shared__ __align__(16) char smem[];
    const uint32_t sb = smem_u32(smem);
    const int tid = threadIdx.x;
    const int lane = tid & 31;
    const int rg = (tid >> 5) & 3;     // row group (32 nodes)
    const int cq = tid >> 7;           // chunk quad-half (j-tiles 4cq..4cq+3)
    const int tileBase = blockIdx.x * 128;

    float* bs = (float*)(smem + OFF_BIAS);
    for (int i = tid; i < 512; i += 256) bs[i] = g_bsum[i];

    // ---- A assembly: [128 rows][192 k] hi/lo ----
    for (int p = tid; p < 4096; p += 256) {        // x part: k 0..63 (convert)
        int row = p >> 5;
        int kp  = (p & 31) * 2;
        int gnode = start + tileBase + row;
        float2 xv = *(const float2*)(x + (size_t)gnode * 64 + kp);
        __nv_bfloat16 h0, l0, h1, l1;
        split2(xv.x, h0, l0);
        split2(xv.y, h1, l1);
        __nv_bfloat162 hp = {h0, h1}, lp = {l0, l1};
        *(uint32_t*)(smem + OFF_AHI + row * RS + kp * 2) = *(uint32_t*)&hp;
        *(uint32_t*)(smem + OFF_ALO + row * RS + kp * 2) = *(uint32_t*)&lp;
    }
    if (!isLeaf) {                                  // h part: k 64..191, cp.async
        for (int p = tid; p < 2048; p += 256) {
            int row = p >> 4;
            int u   = p & 15;                       // 0..7 left, 8..15 right
            int gnode = start + tileBase + row;
            int child = (u < 8) ? (2 * gnode + 1) : (2 * gnode + 2);
            int uu = u & 7;
            uint32_t da = sb + (uint32_t)(row * RS + 128 + u * 16);
            cp_async16(da + OFF_AHI, g_hh + (size_t)child * 64 + uu * 8);
            cp_async16(da + OFF_ALO, g_hl + (size_t)child * 64 + uu * 8);
        }
    } else {
        for (int p = tid; p < 2048; p += 256) {
            int row = p >> 4;
            int u   = p & 15;
            uint4 z = make_uint4(0, 0, 0, 0);
            *(uint4*)(smem + OFF_AHI + row * RS + 128 + u * 16) = z;
            *(uint4*)(smem + OFF_ALO + row * RS + 128 + u * 16) = z;
        }
    }

    // ---- B chunk prefetch (64 gates x 192 k, hi+lo) into buf ----
    auto issue_b = [&](int nc, int buf) {
        uint32_t bo = sb + OFF_B + (uint32_t)buf * BUF_SZ;
        #pragma unroll
        for (int it = 0; it < 6; ++it) {
            int p = tid + it * 256;                // p < 1536
            int rr = p / 24, u = p - rr * 24;
            int j = rr >> 3, w = rr & 7;
            int gate = ((j & 3) << 7) + (nc << 4) + ((j >> 2) << 3) + w;
            uint32_t da = bo + (uint32_t)(rr * RS + u * 16);
            cp_async16(da,         g_Whi + (size_t)gate * 192 + u * 8);
            cp_async16(da + 25600, g_Wlo + (size_t)gate * 192 + u * 8);
        }
    };

    issue_b(0, 0);          // group 0 = A h-parts + B chunk 0
    cp_async_commit();

    // per-lane ldmatrix bases
    const uint32_t aHi = sb + OFF_AHI +
        (uint32_t)((rg * 32 + (lane & 15)) * RS + ((lane >> 4) << 4));
    const uint32_t aLo = aHi + (OFF_ALO - OFF_AHI);
    // B x4 covers 2 k-steps: lane octet -> k byte-block 0/16/32/48
    const uint32_t bBase = sb + OFF_B +
        (uint32_t)(cq * 32 * RS + (lane & 7) * RS + ((lane >> 3) << 4));
    const int r0   = rg * 32 + (lane >> 2);
    const int huL0 = (lane & 3) * 2;

    for (int nc = 0; nc < 8; ++nc) {
        if (nc < 7) {
            issue_b(nc + 1, (nc + 1) & 1);
            cp_async_commit();
            asm volatile("cp.async.wait_group 1;" ::: "memory");
        } else {
            asm volatile("cp.async.wait_group 0;" ::: "memory");
        }
        __syncthreads();    // chunk nc data visible to all warps

        const uint32_t bHi = bBase + (uint32_t)(nc & 1) * BUF_SZ;
        const uint32_t bLo = bHi + 25600;

        float acc[2][4][4];
        #pragma unroll
        for (int m = 0; m < 2; ++m)
            #pragma unroll
            for (int j = 0; j < 4; ++j)
                #pragma unroll
                for (int c = 0; c < 4; ++c) acc[m][j][c] = 0.f;

        #pragma unroll
        for (int dk = 0; dk < 6; ++dk) {
            uint32_t ah[2][2][4], al[2][2][4];
            #pragma unroll
            for (int m = 0; m < 2; ++m) {
                ldsm_x4(ah[m][0], aHi + m * (16 * RS) + dk * 64);
                ldsm_x4(ah[m][1], aHi + m * (16 * RS) + dk * 64 + 32);
                ldsm_x4(al[m][0], aLo + m * (16 * RS) + dk * 64);
                ldsm_x4(al[m][1], aLo + m * (16 * RS) + dk * 64 + 32);
            }
            #pragma unroll
            for (int jj = 0; jj < 4; ++jj) {
                uint32_t bh[4], bl[4];
                ldsm_x4(bh, bHi + jj * (8 * RS) + dk * 64);
                ldsm_x4(bl, bLo + jj * (8 * RS) + dk * 64);
                #pragma unroll
                for (int m = 0; m < 2; ++m) {
                    mma_bf16(acc[m][jj], ah[m][0], bh);
                    mma_bf16(acc[m][jj], al[m][0], bh);
                    mma_bf16(acc[m][jj], ah[m][0], bl);
                    mma_bf16(acc[m][jj], ah[m][1], bh + 2);
                    mma_bf16(acc[m][jj], al[m][1], bh + 2);
                    mma_bf16(acc[m][jj], ah[m][1], bl + 2);
                }
            }
        }

        // ---- fused LSTM epilogue: warp owns full (i,f,g,o) quad ----
        const int hu = (nc << 4) + (cq << 3) + huL0;   // even pair {hu, hu+1}
        #pragma unroll
        for (int m = 0; m < 2; ++m) {
            #pragma unroll
            for (int rh = 0; rh < 2; ++rh) {
                const int row = r0 + m * 16 + 8 * rh;
                const int gnode = start + tileBase + row;
                float2 cp = make_float2(0.f, 0.f);
                if (!isLeaf) {
                    int child = (hu < 64) ? (2 * gnode + 1) : (2 * gnode + 2);
                    cp = *(const float2*)(g_c + (size_t)child * 64 + (hu & 63));
                }
                float gi0 = acc[m][0][2 * rh]     + bs[hu];
                float gi1 = acc[m][0][2 * rh + 1] + bs[hu + 1];
                float gf0 = acc[m][1][2 * rh]     + bs[128 + hu];
                float gf1 = acc[m][1][2 * rh + 1] + bs[128 + hu + 1];
                float gg0 = acc[m][2][2 * rh]     + bs[256 + hu];
                float gg1 = acc[m][2][2 * rh + 1] + bs[256 + hu + 1];
                float go0 = acc[m][3][2 * rh]     + bs[384 + hu];
                float go1 = acc[m][3][2 * rh + 1] + bs[384 + hu + 1];
                float c0 = sigf(gf0) * cp.x + sigf(gi0) * tanha(gg0);
                float c1 = sigf(gf1) * cp.y + sigf(gi1) * tanha(gg1);
                float h0 = sigf(go0) * tanha(c0);
                float h1 = sigf(go1) * tanha(c1);
                *(float2*)(out + (size_t)gnode * 128 + hu) = make_float2(h0, h1);
                if (hu < 64) {
                    *(float2*)(g_c + (size_t)gnode * 64 + hu) = make_float2(c0, c1);
                    __nv_bfloat16 hh0, hl0, hh1, hl1;
                    split2(h0, hh0, hl0);
                    split2(h1, hh1, hl1);
                    __nv_bfloat162 hp = {hh0, hh1}, lp = {hl0, hl1};
                    *(uint32_t*)(g_hh + (size_t)gnode * 64 + hu) = *(uint32_t*)&hp;
                    *(uint32_t*)(g_hl + (size_t)gnode * 64 + hu) = *(uint32_t*)&lp;
                }
            }
        }
        __syncthreads();    // all warps done with buf[nc&1] before reuse
    }
}

// =====================================================================
// Small-level SIMT kernel: 8 nodes per 256-thread block.
// =====================================================================
__global__ __launch_bounds__(256, 4)
void lstm_small_kernel(const float* __restrict__ x,
                       const float* __restrict__ Wih,
                       const float* __restrict__ Whh,
                       const float* __restrict__ bih,
                       const float* __restrict__ bhh,
                       float* __restrict__ out,
                       int start, int count, int isLeaf)
{
    __shared__ __align__(16) float As[8][196];
    __shared__ __align__(16) float Cs[8][128];
    __shared__ float bsm[512];

    const int t = threadIdx.x;
    const int tileBase = blockIdx.x * 8;

    for (int i = t; i < 512; i += 256) bsm[i] = bih[i] + bhh[i];

    for (int q = t; q < 384; q += 256) {
        int node = q / 48, c4 = q - node * 48, col = c4 * 4;
        float4 v = make_float4(0.f, 0.f, 0.f, 0.f);
        int nodeIdx = tileBase + node;
        if (nodeIdx < count) {
            int gnode = start + nodeIdx;
            if (col < 64) {
                v = *(const float4*)(x + (size_t)gnode * 64 + col);
            } else if (!isLeaf) {
                int child = (col < 128) ? (2 * gnode + 1) : (2 * gnode + 2);
                int cc    = (col < 128) ? (col - 64) : (col - 128);
                v = *(const float4*)(out + (size_t)child * 128 + cc);
            }
        }
        *(float4*)&As[node][col] = v;
    }
    {
        int node = t / 32, col = (t & 31) * 4;
        float4 v = make_float4(0.f, 0.f, 0.f, 0.f);
        int nodeIdx = tileBase + node;
        if (nodeIdx < count && !isLeaf) {
            int gnode = start + nodeIdx;
            int child = (col < 64) ? (2 * gnode + 1) : (2 * gnode + 2);
            int cc    = (col < 64) ? col : (col - 64);
            v = *(const float4*)&g_c[(size_t)child * 64 + cc];
        }
        *(float4*)&Cs[node][col] = v;
    }
    __syncthreads();

    const int hu = t & 127;
    const int np = t >> 7;
    float acc[4][4];
    #pragma unroll
    for (int n = 0; n < 4; ++n)
        #pragma unroll
        for (int g = 0; g < 4; ++g)
            acc[n][g] = bsm[hu + g * 128];

    for (int kc = 0; kc < 48; ++kc) {
        const int k0 = kc * 4;
        float4 w[4];
        #pragma unroll
        for (int g = 0; g < 4; ++g) {
            int grow = hu + g * 128;
            w[g] = (k0 < 64)
                 ? *(const float4*)(Wih + (size_t)grow * 64 + k0)
                 : *(const float4*)(Whh + (size_t)grow * 128 + (k0 - 64));
        }
        #pragma unroll
        for (int n = 0; n < 4; ++n) {
            float4 a = *(const float4*)&As[np + 2 * n][k0];
            #pragma unroll
            for (int g = 0; g < 4; ++g)
                acc[n][g] += a.x * w[g].x + a.y * w[g].y + a.z * w[g].z + a.w * w[g].w;
        }
    }

    #pragma unroll
    for (int n = 0; n < 4; ++n) {
        int nn = np + 2 * n;
        int nodeIdx = tileBase + nn;
        if (nodeIdx < count) {
            int gnode = start + nodeIdx;
            float cp = Cs[nn][hu];
            float c = sigf(acc[n][1]) * cp + sigf(acc[n][0]) * tanha(acc[n][2]);
            float h = sigf(acc[n][3]) * tanha(c);
            out[(size_t)gnode * 128 + hu] = h;
            if (hu < 64) g_c[(size_t)gnode * 64 + hu] = c;
        }
    }
}

extern "C" void kernel_launch(void* const* d_in, const int* in_sizes, int n_in,
                              void* d_out, int out_size)
{
    const float* x   = (const float*)d_in[0];   // [262143, 64]
    const float* Wih = (const float*)d_in[1];   // [512, 64]
    const float* Whh = (const float*)d_in[2];   // [512, 128]
    const float* bih = (const float*)d_in[3];   // [512]
    const float* bhh = (const float*)d_in[4];   // [512]
    float* out = (float*)d_out;                 // [262143, 128]

    static bool attr_done = false;
    if (!attr_done) {
        cudaFuncSetAttribute(lstm_tc_kernel,
                             cudaFuncAttributeMaxDynamicSharedMemorySize, SMEM_TC);
        attr_done = true;
    }

    prep_kernel<<<96, 256>>>(Wih, Whh, bih, bhh);

    for (int lvl = LEVELS - 1; lvl >= 0; --lvl) {
        int start = (1 << lvl) - 1;
        int count = 1 << lvl;
        int isLeaf = (lvl == LEVELS - 1);
        if (count >= 2048) {
            lstm_tc_kernel<<<count / 128, 256, SMEM_TC>>>(x, out, start, isLeaf);
        } else {
            lstm_small_kernel<<<(count + 7) / 8, 256>>>(
                x, Wih, Whh, bih, bhh, out, start, count, isLeaf);
        }
    }
}

// round 7
// speedup vs baseline: 1.0972x; 1.0972x over previous
#include <cuda_runtime.h>
#include <cuda_bf16.h>
#include <cstdint>

#define LEVELS 18
#define NNODES ((1 << LEVELS) - 1)

// Persisted state + preconverted weights (device globals; no runtime alloc).
__device__ float         g_c   [(size_t)NNODES * 64];  // cell state, cols 0..63 only
__device__ __nv_bfloat16 g_hh  [(size_t)NNODES * 64];  // h bf16 hi, cols 0..63
__device__ __nv_bfloat16 g_hl  [(size_t)NNODES * 64];  // h bf16 lo
__device__ __nv_bfloat16 g_Whi [512 * 192];            // [gate][k] concat(Wih,Whh) hi
__device__ __nv_bfloat16 g_Wlo [512 * 192];            // lo
__device__ float         g_bsum[512];

// ------------------------------------------------------------------ helpers
__device__ __forceinline__ uint32_t smem_u32(const void* p) {
    uint32_t a;
    asm("{ .reg .u64 t; cvta.to.shared.u64 t, %1; cvt.u32.u64 %0, t; }"
        : "=r"(a) : "l"(p));
    return a;
}
__device__ __forceinline__ void ldsm_x4(uint32_t* r, uint32_t addr) {
    asm volatile("ldmatrix.sync.aligned.m8n8.x4.shared.b16 {%0,%1,%2,%3}, [%4];"
                 : "=r"(r[0]), "=r"(r[1]), "=r"(r[2]), "=r"(r[3]) : "r"(addr));
}
__device__ __forceinline__ void mma_bf16(float* d, const uint32_t* a, const uint32_t* b) {
    asm volatile("mma.sync.aligned.m16n8k16.row.col.f32.bf16.bf16.f32 "
                 "{%0,%1,%2,%3}, {%4,%5,%6,%7}, {%8,%9}, {%0,%1,%2,%3};"
                 : "+f"(d[0]), "+f"(d[1]), "+f"(d[2]), "+f"(d[3])
                 : "r"(a[0]), "r"(a[1]), "r"(a[2]), "r"(a[3]), "r"(b[0]), "r"(b[1]));
}
__device__ __forceinline__ void cp_async16(uint32_t saddr, const void* g) {
    asm volatile("cp.async.ca.shared.global [%0], [%1], 16;"
                 :: "r"(saddr), "l"(g) : "memory");
}
__device__ __forceinline__ void cp_async_commit() {
    asm volatile("cp.async.commit_group;" ::: "memory");
}
__device__ __forceinline__ void split2(float v, __nv_bfloat16& hi, __nv_bfloat16& lo) {
    hi = __float2bfloat16(v);
    lo = __float2bfloat16(v - __bfloat162float(hi));
}
__device__ __forceinline__ float sigf(float z) {
    return __fdividef(1.0f, 1.0f + __expf(-z));
}
__device__ __forceinline__ float tanha(float z) {
    return __fdividef(2.0f, 1.0f + __expf(-2.0f * z)) - 1.0f;
}

// ---------------------------------------------------------------- SMEM plan
// Row stride 400B: rows hit distinct bank quads -> conflict-free ldmatrix.
#define RS 400
#define OFF_BIAS 0
#define OFF_AHI  2048
#define OFF_ALO  (OFF_AHI + 128 * RS)   // 53248
#define OFF_B    (OFF_ALO + 128 * RS)   // 104448; buf b: hi at +b*51200, lo +25600
#define BUF_SZ   51200
#define SMEM_TC  (OFF_B + 2 * BUF_SZ)   // 206848 (1 CTA/SM, 16 warps)

// ---------------------------------------------------------------- prep
__global__ void prep_kernel(const float* __restrict__ Wih,
                            const float* __restrict__ Whh,
                            const float* __restrict__ bih,
                            const float* __restrict__ bhh)
{
    int idx = blockIdx.x * blockDim.x + threadIdx.x;
    if (idx < 512) g_bsum[idx] = bih[idx] + bhh[idx];
    for (int p = idx; p < 512 * 192; p += gridDim.x * blockDim.x) {
        int g = p / 192, k = p - g * 192;
        float v = (k < 64) ? Wih[g * 64 + k] : Whh[g * 128 + (k - 64)];
        __nv_bfloat16 hi, lo;
        split2(v, hi, lo);
        g_Whi[p] = hi;
        g_Wlo[p] = lo;
    }
}

// =====================================================================
// Tensor-core level kernel: CTA = 128 nodes x 512 gates, 512 threads,
// 16 warps = 8 row-groups (16 nodes) x 2 chunk-halves (4 j-tiles).
// 8 gate-chunks of 64, double-buffered via cp.async, ONE sync per chunk:
//   wait(buf nc) -> sync -> issue buf nc+1 -> MMA(buf nc) + epilogue.
// Chunk tile j (0..7): gate type j&3, hu octet j>>2. Warp ch owns
// j = 4ch..4ch+3 = full (i,f,g,o) quad -> register-local epilogue.
// B row rr=8j+p -> gate ((j&3)<<7) + nc*16 + ((j>>2)<<3) + p.
// =====================================================================
__global__ __launch_bounds__(512, 1)
void lstm_tc_kernel(const float* __restrict__ x,
                    float* __restrict__ out,
                    int start, int isLeaf)
{
    extern __shared__ __align__(16) char smem[];
    const uint32_t sb = smem_u32(smem);
    const int tid = threadIdx.x;
    const int lane = tid & 31;
    const int rg = (tid >> 5) & 7;     // row group (16 nodes)
    const int ch = tid >> 8;           // chunk half (j-tiles 4ch..4ch+3)
    const int tileBase = blockIdx.x * 128;

    float* bs = (float*)(smem + OFF_BIAS);
    if (tid < 512) bs[tid] = g_bsum[tid];

    // ---- A assembly: [128 rows][192 k] hi/lo ----
    for (int p = tid; p < 4096; p += 512) {        // x part: k 0..63 (convert)
        int row = p >> 5;
        int kp  = (p & 31) * 2;
        int gnode = start + tileBase + row;
        float2 xv = *(const float2*)(x + (size_t)gnode * 64 + kp);
        __nv_bfloat16 h0, l0, h1, l1;
        split2(xv.x, h0, l0);
        split2(xv.y, h1, l1);
        __nv_bfloat162 hp = {h0, h1}, lp = {l0, l1};
        *(uint32_t*)(smem + OFF_AHI + row * RS + kp * 2) = *(uint32_t*)&hp;
        *(uint32_t*)(smem + OFF_ALO + row * RS + kp * 2) = *(uint32_t*)&lp;
    }
    if (!isLeaf) {                                  // h part: k 64..191, cp.async
        for (int p = tid; p < 2048; p += 512) {
            int row = p >> 4;
            int u   = p & 15;                       // 0..7 left, 8..15 right
            int gnode = start + tileBase + row;
            int child = (u < 8) ? (2 * gnode + 1) : (2 * gnode + 2);
            int uu = u & 7;
            uint32_t da = sb + (uint32_t)(row * RS + 128 + u * 16);
            cp_async16(da + OFF_AHI, g_hh + (size_t)child * 64 + uu * 8);
            cp_async16(da + OFF_ALO, g_hl + (size_t)child * 64 + uu * 8);
        }
    } else {
        for (int p = tid; p < 2048; p += 512) {
            int row = p >> 4;
            int u   = p & 15;
            uint4 z = make_uint4(0, 0, 0, 0);
            *(uint4*)(smem + OFF_AHI + row * RS + 128 + u * 16) = z;
            *(uint4*)(smem + OFF_ALO + row * RS + 128 + u * 16) = z;
        }
    }

    // ---- B chunk prefetch (64 gates x 192 k, hi+lo) into buf ----
    auto issue_b = [&](int nc, int buf) {
        uint32_t bo = sb + OFF_B + (uint32_t)buf * BUF_SZ;
        #pragma unroll
        for (int it = 0; it < 3; ++it) {
            int p = tid + it * 512;                // p < 1536
            int rr = p / 24, u = p - rr * 24;
            int j = rr >> 3, w = rr & 7;
            int gate = ((j & 3) << 7) + (nc << 4) + ((j >> 2) << 3) + w;
            uint32_t da = bo + (uint32_t)(rr * RS + u * 16);
            cp_async16(da,         g_Whi + (size_t)gate * 192 + u * 8);
            cp_async16(da + 25600, g_Wlo + (size_t)gate * 192 + u * 8);
        }
    };

    issue_b(0, 0);          // group 0 = A h-parts + B chunk 0
    cp_async_commit();

    // per-lane ldmatrix bases
    const uint32_t aHi = sb + OFF_AHI +
        (uint32_t)((rg * 16 + (lane & 15)) * RS + ((lane >> 4) << 4));
    const uint32_t aLo = aHi + (OFF_ALO - OFF_AHI);
    // B x4 covers 2 k-steps: lane octet -> k byte-block 0/16/32/48
    const uint32_t bBase = sb + OFF_B +
        (uint32_t)(ch * 32 * RS + (lane & 7) * RS + ((lane >> 3) << 4));
    const int r0   = rg * 16 + (lane >> 2);
    const int huL0 = (lane & 3) * 2;

    for (int nc = 0; nc < 8; ++nc) {
        asm volatile("cp.async.wait_group 0;" ::: "memory");  // buf nc ready
        __syncthreads();   // all warps: see buf nc; done reading buf nc-1's slot
        if (nc < 7) {      // prefetch next chunk under this chunk's MMA
            issue_b(nc + 1, (nc + 1) & 1);
            cp_async_commit();
        }

        const uint32_t bHi = bBase + (uint32_t)(nc & 1) * BUF_SZ;
        const uint32_t bLo = bHi + 25600;

        float acc[4][4];
        #pragma unroll
        for (int j = 0; j < 4; ++j)
            #pragma unroll
            for (int c = 0; c < 4; ++c) acc[j][c] = 0.f;

        #pragma unroll
        for (int dk = 0; dk < 6; ++dk) {
            uint32_t ah0[4], al0[4], ah1[4], al1[4];
            ldsm_x4(ah0, aHi + dk * 64);
            ldsm_x4(al0, aLo + dk * 64);
            ldsm_x4(ah1, aHi + dk * 64 + 32);
            ldsm_x4(al1, aLo + dk * 64 + 32);
            #pragma unroll
            for (int jj = 0; jj < 4; ++jj) {
                uint32_t bh[4], bl[4];
                ldsm_x4(bh, bHi + jj * (8 * RS) + dk * 64);
                ldsm_x4(bl, bLo + jj * (8 * RS) + dk * 64);
                mma_bf16(acc[jj], ah0, bh);
                mma_bf16(acc[jj], al0, bh);
                mma_bf16(acc[jj], ah0, bl);
                mma_bf16(acc[jj], ah1, bh + 2);
                mma_bf16(acc[jj], al1, bh + 2);
                mma_bf16(acc[jj], ah1, bl + 2);
            }
        }

        // ---- fused LSTM epilogue: this warp owns full (i,f,g,o) quad ----
        const int hu = (nc << 4) + (ch << 3) + huL0;   // even pair {hu, hu+1}
        #pragma unroll
        for (int rh = 0; rh < 2; ++rh) {
            const int row = r0 + 8 * rh;
            const int gnode = start + tileBase + row;
            float2 cp = make_float2(0.f, 0.f);
            if (!isLeaf) {
                int child = (hu < 64) ? (2 * gnode + 1) : (2 * gnode + 2);
                cp = *(const float2*)(g_c + (size_t)child * 64 + (hu & 63));
            }
            float gi0 = acc[0][2 * rh]     + bs[hu];
            float gi1 = acc[0][2 * rh + 1] + bs[hu + 1];
            float gf0 = acc[1][2 * rh]     + bs[128 + hu];
            float gf1 = acc[1][2 * rh + 1] + bs[128 + hu + 1];
            float gg0 = acc[2][2 * rh]     + bs[256 + hu];
            float gg1 = acc[2][2 * rh + 1] + bs[256 + hu + 1];
            float go0 = acc[3][2 * rh]     + bs[384 + hu];
            float go1 = acc[3][2 * rh + 1] + bs[384 + hu + 1];
            float c0 = sigf(gf0) * cp.x + sigf(gi0) * tanha(gg0);
            float c1 = sigf(gf1) * cp.y + sigf(gi1) * tanha(gg1);
            float h0 = sigf(go0) * tanha(c0);
            float h1 = sigf(go1) * tanha(c1);
            *(float2*)(out + (size_t)gnode * 128 + hu) = make_float2(h0, h1);
            if (hu < 64) {
                *(float2*)(g_c + (size_t)gnode * 64 + hu) = make_float2(c0, c1);
                __nv_bfloat16 hh0, hl0, hh1, hl1;
                split2(h0, hh0, hl0);
                split2(h1, hh1, hl1);
                __nv_bfloat162 hp = {hh0, hh1}, lp = {hl0, hl1};
                *(uint32_t*)(g_hh + (size_t)gnode * 64 + hu) = *(uint32_t*)&hp;
                *(uint32_t*)(g_hl + (size_t)gnode * 64 + hu) = *(uint32_t*)&lp;
            }
        }
    }
}

// =====================================================================
// Small-level SIMT kernel: 8 nodes per 256-thread block.
// =====================================================================
__global__ __launch_bounds__(256, 4)
void lstm_small_kernel(const float* __restrict__ x,
                       const float* __restrict__ Wih,
                       const float* __restrict__ Whh,
                       const float* __restrict__ bih,
                       const float* __restrict__ bhh,
                       float* __restrict__ out,
                       int start, int count, int isLeaf)
{
    __shared__ __align__(16) float As[8][196];
    __shared__ __align__(16) float Cs[8][128];
    __shared__ float bsm[512];

    const int t = threadIdx.x;
    const int tileBase = blockIdx.x * 8;

    for (int i = t; i < 512; i += 256) bsm[i] = bih[i] + bhh[i];

    for (int q = t; q < 384; q += 256) {
        int node = q / 48, c4 = q - node * 48, col = c4 * 4;
        float4 v = make_float4(0.f, 0.f, 0.f, 0.f);
        int nodeIdx = tileBase + node;
        if (nodeIdx < count) {
            int gnode = start + nodeIdx;
            if (col < 64) {
                v = *(const float4*)(x + (size_t)gnode * 64 + col);
            } else if (!isLeaf) {
                int child = (col < 128) ? (2 * gnode + 1) : (2 * gnode + 2);
                int cc    = (col < 128) ? (col - 64) : (col - 128);
                v = *(const float4*)(out + (size_t)child * 128 + cc);
            }
        }
        *(float4*)&As[node][col] = v;
    }
    {
        int node = t / 32, col = (t & 31) * 4;
        float4 v = make_float4(0.f, 0.f, 0.f, 0.f);
        int nodeIdx = tileBase + node;
        if (nodeIdx < count && !isLeaf) {
            int gnode = start + nodeIdx;
            int child = (col < 64) ? (2 * gnode + 1) : (2 * gnode + 2);
            int cc    = (col < 64) ? col : (col - 64);
            v = *(const float4*)&g_c[(size_t)child * 64 + cc];
        }
        *(float4*)&Cs[node][col] = v;
    }
    __syncthreads();

    const int hu = t & 127;
    const int np = t >> 7;
    float acc[4][4];
    #pragma unroll
    for (int n = 0; n < 4; ++n)
        #pragma unroll
        for (int g = 0; g < 4; ++g)
            acc[n][g] = bsm[hu + g * 128];

    for (int kc = 0; kc < 48; ++kc) {
        const int k0 = kc * 4;
        float4 w[4];
        #pragma unroll
        for (int g = 0; g < 4; ++g) {
            int grow = hu + g * 128;
            w[g] = (k0 < 64)
                 ? *(const float4*)(Wih + (size_t)grow * 64 + k0)
                 : *(const float4*)(Whh + (size_t)grow * 128 + (k0 - 64));
        }
        #pragma unroll
        for (int n = 0; n < 4; ++n) {
            float4 a = *(const float4*)&As[np + 2 * n][k0];
            #pragma unroll
            for (int g = 0; g < 4; ++g)
                acc[n][g] += a.x * w[g].x + a.y * w[g].y + a.z * w[g].z + a.w * w[g].w;
        }
    }

    #pragma unroll
    for (int n = 0; n < 4; ++n) {
        int nn = np + 2 * n;
        int nodeIdx = tileBase + nn;
        if (nodeIdx < count) {
            int gnode = start + nodeIdx;
            float cp = Cs[nn][hu];
            float c = sigf(acc[n][1]) * cp + sigf(acc[n][0]) * tanha(acc[n][2]);
            float h = sigf(acc[n][3]) * tanha(c);
            out[(size_t)gnode * 128 + hu] = h;
            if (hu < 64) g_c[(size_t)gnode * 64 + hu] = c;
        }
    }
}

extern "C" void kernel_launch(void* const* d_in, const int* in_sizes, int n_in,
                              void* d_out, int out_size)
{
    const float* x   = (const float*)d_in[0];   // [262143, 64]
    const float* Wih = (const float*)d_in[1];   // [512, 64]
    const float* Whh = (const float*)d_in[2];   // [512, 128]
    const float* bih = (const float*)d_in[3];   // [512]
    const float* bhh = (const float*)d_in[4];   // [512]
    float* out = (float*)d_out;                 // [262143, 128]

    static bool attr_done = false;
    if (!attr_done) {
        cudaFuncSetAttribute(lstm_tc_kernel,
                             cudaFuncAttributeMaxDynamicSharedMemorySize, SMEM_TC);
        attr_done = true;
    }

    prep_kernel<<<96, 256>>>(Wih, Whh, bih, bhh);

    for (int lvl = LEVELS - 1; lvl >= 0; --lvl) {
        int start = (1 << lvl) - 1;
        int count = 1 << lvl;
        int isLeaf = (lvl == LEVELS - 1);
        if (count >= 1024) {
            lstm_tc_kernel<<<count / 128, 512, SMEM_TC>>>(x, out, start, isLeaf);
        } else {
            lstm_small_kernel<<<(count + 7) / 8, 256>>>(
                x, Wih, Whh, bih, bhh, out, start, count, isLeaf);
        }
    }
}

// round 8
// speedup vs baseline: 1.3127x; 1.1964x over previous
#include <cuda_runtime.h>
#include <cuda_fp16.h>
#include <cstdint>

#define LEVELS 18
#define NNODES ((1 << LEVELS) - 1)

// Persisted state + preconverted weights (device globals; no runtime alloc).
__device__ float  g_c [(size_t)NNODES * 64];   // cell state, cols 0..63 only
__device__ __half g_hh[(size_t)NNODES * 64];   // h fp16 hi, cols 0..63
__device__ __half g_hl[(size_t)NNODES * 64];   // h fp16 lo (residual)
__device__ __half g_W [512 * 192];             // [gate][k] concat(Wih,Whh) fp16
__device__ float  g_bsum[512];

// ------------------------------------------------------------------ helpers
__device__ __forceinline__ uint32_t smem_u32(const void* p) {
    uint32_t a;
    asm("{ .reg .u64 t; cvta.to.shared.u64 t, %1; cvt.u32.u64 %0, t; }"
        : "=r"(a) : "l"(p));
    return a;
}
__device__ __forceinline__ void ldsm_x4(uint32_t* r, uint32_t addr) {
    asm volatile("ldmatrix.sync.aligned.m8n8.x4.shared.b16 {%0,%1,%2,%3}, [%4];"
                 : "=r"(r[0]), "=r"(r[1]), "=r"(r[2]), "=r"(r[3]) : "r"(addr));
}
__device__ __forceinline__ void mma_f16(float* d, const uint32_t* a, const uint32_t* b) {
    asm volatile("mma.sync.aligned.m16n8k16.row.col.f32.f16.f16.f32 "
                 "{%0,%1,%2,%3}, {%4,%5,%6,%7}, {%8,%9}, {%0,%1,%2,%3};"
                 : "+f"(d[0]), "+f"(d[1]), "+f"(d[2]), "+f"(d[3])
                 : "r"(a[0]), "r"(a[1]), "r"(a[2]), "r"(a[3]), "r"(b[0]), "r"(b[1]));
}
__device__ __forceinline__ void cp_async16(uint32_t saddr, const void* g) {
    asm volatile("cp.async.ca.shared.global [%0], [%1], 16;"
                 :: "r"(saddr), "l"(g) : "memory");
}
__device__ __forceinline__ void cp_async_commit() {
    asm volatile("cp.async.commit_group;" ::: "memory");
}
__device__ __forceinline__ void split2h(float v, __half& hi, __half& lo) {
    hi = __float2half_rn(v);
    lo = __float2half_rn(v - __half2float(hi));
}
__device__ __forceinline__ float sigf(float z) {
    return __fdividef(1.0f, 1.0f + __expf(-z));
}
__device__ __forceinline__ float tanha(float z) {
    return __fdividef(2.0f, 1.0f + __expf(-2.0f * z)) - 1.0f;
}

// ---------------------------------------------------------------- SMEM plan
// Row stride 400B: rows hit distinct bank quads -> conflict-free ldmatrix.
#define RS 400
#define OFF_BIAS 0
#define OFF_AHI  2048
#define OFF_ALO  (OFF_AHI + 128 * RS)   // 53248
#define OFF_B    (OFF_ALO + 128 * RS)   // 104448; two buffers of 25600
#define BUF_SZ   25600
#define OFF_C    (OFF_B + 2 * BUF_SZ)   // 155648; c_prev tile [128][132] fp32
#define CTS      528                     // c tile row stride bytes (132 words)
#define SMEM_TC  (OFF_C + 128 * CTS)     // 223232 (1 CTA/SM, 16 warps)

// ---------------------------------------------------------------- prep
__global__ void prep_kernel(const float* __restrict__ Wih,
                            const float* __restrict__ Whh,
                            const float* __restrict__ bih,
                            const float* __restrict__ bhh)
{
    int idx = blockIdx.x * blockDim.x + threadIdx.x;
    if (idx < 512) g_bsum[idx] = bih[idx] + bhh[idx];
    for (int p = idx; p < 512 * 192; p += gridDim.x * blockDim.x) {
        int g = p / 192, k = p - g * 192;
        float v = (k < 64) ? Wih[g * 64 + k] : Whh[g * 128 + (k - 64)];
        g_W[p] = __float2half_rn(v);
    }
}

// =====================================================================
// Tensor-core level kernel: CTA = 128 nodes x 512 gates, 512 threads,
// 16 warps = 8 row-groups (16 nodes) x 2 chunk-halves (4 j-tiles).
// fp16 2-term emulation: gates = (Ahi + Alo) * W_fp16, fp32 accum.
// 8 gate-chunks of 64, double-buffered cp.async, one sync per chunk.
// Chunk tile j (0..7): gate type j&3, hu octet j>>2. Warp ch owns
// j = 4ch..4ch+3 = full (i,f,g,o) quad -> register-local epilogue.
// B row rr=8j+p -> gate ((j&3)<<7) + nc*16 + ((j>>2)<<3) + p.
// =====================================================================
__global__ __launch_bounds__(512, 1)
void lstm_tc_kernel(const float* __restrict__ x,
                    float* __restrict__ out,
                    int start, int isLeaf)
{
    extern __shared__ __align__(16) char smem[];
    const uint32_t sb = smem_u32(smem);
    const int tid = threadIdx.x;
    const int lane = tid & 31;
    const int rg = (tid >> 5) & 7;     // row group (16 nodes)
    const int ch = tid >> 8;           // chunk half (j-tiles 4ch..4ch+3)
    const int tileBase = blockIdx.x * 128;

    float* bs = (float*)(smem + OFF_BIAS);
    if (tid < 512) bs[tid] = g_bsum[tid];

    // ---- A assembly: [128 rows][192 k] fp16 hi/lo ----
    for (int p = tid; p < 4096; p += 512) {        // x part: k 0..63 (convert)
        int row = p >> 5;
        int kp  = (p & 31) * 2;
        int gnode = start + tileBase + row;
        float2 xv = *(const float2*)(x + (size_t)gnode * 64 + kp);
        __half h0, l0, h1, l1;
        split2h(xv.x, h0, l0);
        split2h(xv.y, h1, l1);
        __half2 hp = {h0, h1}, lp = {l0, l1};
        *(uint32_t*)(smem + OFF_AHI + row * RS + kp * 2) = *(uint32_t*)&hp;
        *(uint32_t*)(smem + OFF_ALO + row * RS + kp * 2) = *(uint32_t*)&lp;
    }
    if (!isLeaf) {                                  // h part: k 64..191, cp.async
        for (int p = tid; p < 2048; p += 512) {
            int row = p >> 4;
            int u   = p & 15;                       // 0..7 left, 8..15 right
            int gnode = start + tileBase + row;
            int child = (u < 8) ? (2 * gnode + 1) : (2 * gnode + 2);
            int uu = u & 7;
            uint32_t da = sb + (uint32_t)(row * RS + 128 + u * 16);
            cp_async16(da + OFF_AHI, g_hh + (size_t)child * 64 + uu * 8);
            cp_async16(da + OFF_ALO, g_hl + (size_t)child * 64 + uu * 8);
        }
        // c_prev tile: [128 rows][128 hu] fp32 (left cols 0..63, right 64..127)
        for (int q = tid; q < 4096; q += 512) {
            int row = q >> 5;
            int c4  = (q & 31) * 4;                 // hu base of float4
            int gnode = start + tileBase + row;
            int child = (c4 < 64) ? (2 * gnode + 1) : (2 * gnode + 2);
            cp_async16(sb + OFF_C + (uint32_t)(row * CTS + c4 * 4),
                       g_c + (size_t)child * 64 + (c4 & 63));
        }
    } else {
        for (int p = tid; p < 2048; p += 512) {
            int row = p >> 4;
            int u   = p & 15;
            uint4 z = make_uint4(0, 0, 0, 0);
            *(uint4*)(smem + OFF_AHI + row * RS + 128 + u * 16) = z;
            *(uint4*)(smem + OFF_ALO + row * RS + 128 + u * 16) = z;
        }
    }

    // ---- B chunk prefetch (64 gates x 192 k fp16) into buf ----
    auto issue_b = [&](int nc, int buf) {
        uint32_t bo = sb + OFF_B + (uint32_t)buf * BUF_SZ;
        #pragma unroll
        for (int it = 0; it < 3; ++it) {
            int p = tid + it * 512;                // p < 1536
            int rr = p / 24, u = p - rr * 24;
            int j = rr >> 3, w = rr & 7;
            int gate = ((j & 3) << 7) + (nc << 4) + ((j >> 2) << 3) + w;
            cp_async16(bo + (uint32_t)(rr * RS + u * 16),
                       g_W + (size_t)gate * 192 + u * 8);
        }
    };

    issue_b(0, 0);          // group 0 = A h-parts + c tile + B chunk 0
    cp_async_commit();

    // per-lane ldmatrix bases
    const uint32_t aHi = sb + OFF_AHI +
        (uint32_t)((rg * 16 + (lane & 15)) * RS + ((lane >> 4) << 4));
    const uint32_t aLo = aHi + (OFF_ALO - OFF_AHI);
    // B x4 covers 2 k-steps: lane octet -> k byte-block 0/16/32/48
    const uint32_t bBase = sb + OFF_B +
        (uint32_t)(ch * 32 * RS + (lane & 7) * RS + ((lane >> 3) << 4));
    const int r0   = rg * 16 + (lane >> 2);
    const int huL0 = (lane & 3) * 2;

    for (int nc = 0; nc < 8; ++nc) {
        asm volatile("cp.async.wait_group 0;" ::: "memory");  // buf nc ready
        __syncthreads();   // all warps see buf nc; prior reads of this slot done
        if (nc < 7) {      // prefetch next chunk under this chunk's MMA
            issue_b(nc + 1, (nc + 1) & 1);
            cp_async_commit();
        }

        const uint32_t bHi = bBase + (uint32_t)(nc & 1) * BUF_SZ;

        float acc[4][4];
        #pragma unroll
        for (int j = 0; j < 4; ++j)
            #pragma unroll
            for (int c = 0; c < 4; ++c) acc[j][c] = 0.f;

        #pragma unroll
        for (int dk = 0; dk < 6; ++dk) {
            uint32_t ah0[4], al0[4], ah1[4], al1[4];
            ldsm_x4(ah0, aHi + dk * 64);
            ldsm_x4(al0, aLo + dk * 64);
            ldsm_x4(ah1, aHi + dk * 64 + 32);
            ldsm_x4(al1, aLo + dk * 64 + 32);
            #pragma unroll
            for (int jj = 0; jj < 4; ++jj) {
                uint32_t bh[4];
                ldsm_x4(bh, bHi + jj * (8 * RS) + dk * 64);
                mma_f16(acc[jj], ah0, bh);
                mma_f16(acc[jj], al0, bh);
                mma_f16(acc[jj], ah1, bh + 2);
                mma_f16(acc[jj], al1, bh + 2);
            }
        }

        // ---- fused LSTM epilogue: this warp owns full (i,f,g,o) quad ----
        const int hu = (nc << 4) + (ch << 3) + huL0;   // even pair {hu, hu+1}
        #pragma unroll
        for (int rh = 0; rh < 2; ++rh) {
            const int row = r0 + 8 * rh;
            const int gnode = start + tileBase + row;
            float2 cp = make_float2(0.f, 0.f);
            if (!isLeaf)
                cp = *(const float2*)(smem + OFF_C + row * CTS + hu * 4);
            float gi0 = acc[0][2 * rh]     + bs[hu];
            float gi1 = acc[0][2 * rh + 1] + bs[hu + 1];
            float gf0 = acc[1][2 * rh]     + bs[128 + hu];
            float gf1 = acc[1][2 * rh + 1] + bs[128 + hu + 1];
            float gg0 = acc[2][2 * rh]     + bs[256 + hu];
            float gg1 = acc[2][2 * rh + 1] + bs[256 + hu + 1];
            float go0 = acc[3][2 * rh]     + bs[384 + hu];
            float go1 = acc[3][2 * rh + 1] + bs[384 + hu + 1];
            float c0 = sigf(gf0) * cp.x + sigf(gi0) * tanha(gg0);
            float c1 = sigf(gf1) * cp.y + sigf(gi1) * tanha(gg1);
            float h0 = sigf(go0) * tanha(c0);
            float h1 = sigf(go1) * tanha(c1);
            *(float2*)(out + (size_t)gnode * 128 + hu) = make_float2(h0, h1);
            if (hu < 64) {
                *(float2*)(g_c + (size_t)gnode * 64 + hu) = make_float2(c0, c1);
                __half hh0, hl0, hh1, hl1;
                split2h(h0, hh0, hl0);
                split2h(h1, hh1, hl1);
                __half2 hp = {hh0, hh1}, lp = {hl0, hl1};
                *(uint32_t*)(g_hh + (size_t)gnode * 64 + hu) = *(uint32_t*)&hp;
                *(uint32_t*)(g_hl + (size_t)gnode * 64 + hu) = *(uint32_t*)&lp;
            }
        }
    }
}

// =====================================================================
// Small-level SIMT kernel: 8 nodes per 256-thread block.
// =====================================================================
__global__ __launch_bounds__(256, 4)
void lstm_small_kernel(const float* __restrict__ x,
                       const float* __restrict__ Wih,
                       const float* __restrict__ Whh,
                       const float* __restrict__ bih,
                       const float* __restrict__ bhh,
                       float* __restrict__ out,
                       int start, int count, int isLeaf)
{
    __shared__ __align__(16) float As[8][196];
    __shared__ __align__(16) float Cs[8][128];
    __shared__ float bsm[512];

    const int t = threadIdx.x;
    const int tileBase = blockIdx.x * 8;

    for (int i = t; i < 512; i += 256) bsm[i] = bih[i] + bhh[i];

    for (int q = t; q < 384; q += 256) {
        int node = q / 48, c4 = q - node * 48, col = c4 * 4;
        float4 v = make_float4(0.f, 0.f, 0.f, 0.f);
        int nodeIdx = tileBase + node;
        if (nodeIdx < count) {
            int gnode = start + nodeIdx;
            if (col < 64) {
                v = *(const float4*)(x + (size_t)gnode * 64 + col);
            } else if (!isLeaf) {
                int child = (col < 128) ? (2 * gnode + 1) : (2 * gnode + 2);
                int cc    = (col < 128) ? (col - 64) : (col - 128);
                v = *(const float4*)(out + (size_t)child * 128 + cc);
            }
        }
        *(float4*)&As[node][col] = v;
    }
    {
        int node = t / 32, col = (t & 31) * 4;
        float4 v = make_float4(0.f, 0.f, 0.f, 0.f);
        int nodeIdx = tileBase + node;
        if (nodeIdx < count && !isLeaf) {
            int gnode = start + nodeIdx;
            int child = (col < 64) ? (2 * gnode + 1) : (2 * gnode + 2);
            int cc    = (col < 64) ? col : (col - 64);
            v = *(const float4*)&g_c[(size_t)child * 64 + cc];
        }
        *(float4*)&Cs[node][col] = v;
    }
    __syncthreads();

    const int hu = t & 127;
    const int np = t >> 7;
    float acc[4][4];
    #pragma unroll
    for (int n = 0; n < 4; ++n)
        #pragma unroll
        for (int g = 0; g < 4; ++g)
            acc[n][g] = bsm[hu + g * 128];

    for (int kc = 0; kc < 48; ++kc) {
        const int k0 = kc * 4;
        float4 w[4];
        #pragma unroll
        for (int g = 0; g < 4; ++g) {
            int grow = hu + g * 128;
            w[g] = (k0 < 64)
                 ? *(const float4*)(Wih + (size_t)grow * 64 + k0)
                 : *(const float4*)(Whh + (size_t)grow * 128 + (k0 - 64));
        }
        #pragma unroll
        for (int n = 0; n < 4; ++n) {
            float4 a = *(const float4*)&As[np + 2 * n][k0];
            #pragma unroll
            for (int g = 0; g < 4; ++g)
                acc[n][g] += a.x * w[g].x + a.y * w[g].y + a.z * w[g].z + a.w * w[g].w;
        }
    }

    #pragma unroll
    for (int n = 0; n < 4; ++n) {
        int nn = np + 2 * n;
        int nodeIdx = tileBase + nn;
        if (nodeIdx < count) {
            int gnode = start + nodeIdx;
            float cp = Cs[nn][hu];
            float c = sigf(acc[n][1]) * cp + sigf(acc[n][0]) * tanha(acc[n][2]);
            float h = sigf(acc[n][3]) * tanha(c);
            out[(size_t)gnode * 128 + hu] = h;
            if (hu < 64) g_c[(size_t)gnode * 64 + hu] = c;
        }
    }
}

extern "C" void kernel_launch(void* const* d_in, const int* in_sizes, int n_in,
                              void* d_out, int out_size)
{
    const float* x   = (const float*)d_in[0];   // [262143, 64]
    const float* Wih = (const float*)d_in[1];   // [512, 64]
    const float* Whh = (const float*)d_in[2];   // [512, 128]
    const float* bih = (const float*)d_in[3];   // [512]
    const float* bhh = (const float*)d_in[4];   // [512]
    float* out = (float*)d_out;                 // [262143, 128]

    static bool attr_done = false;
    if (!attr_done) {
        cudaFuncSetAttribute(lstm_tc_kernel,
                             cudaFuncAttributeMaxDynamicSharedMemorySize, SMEM_TC);
        attr_done = true;
    }

    prep_kernel<<<96, 256>>>(Wih, Whh, bih, bhh);

    for (int lvl = LEVELS - 1; lvl >= 0; --lvl) {
        int start = (1 << lvl) - 1;
        int count = 1 << lvl;
        int isLeaf = (lvl == LEVELS - 1);
        if (count >= 1024) {
            lstm_tc_kernel<<<count / 128, 512, SMEM_TC>>>(x, out, start, isLeaf);
        } else {
            lstm_small_kernel<<<(count + 7) / 8, 256>>>(
                x, Wih, Whh, bih, bhh, out, start, count, isLeaf);
        }
    }
}

// round 9
// speedup vs baseline: 1.5366x; 1.1706x over previous
#include <cuda_runtime.h>
#include <cuda_fp16.h>
#include <cstdint>

#define LEVELS 18
#define NNODES ((1 << LEVELS) - 1)

// Persisted state + preconverted weights (device globals; no runtime alloc).
__device__ float  g_c [(size_t)NNODES * 64];   // cell state, cols 0..63 only
__device__ __half g_hh[(size_t)NNODES * 64];   // h fp16 hi, cols 0..63
__device__ __half g_hl[(size_t)NNODES * 64];   // h fp16 lo (residual)
__device__ __half g_W [512 * 192];             // [gate][k] concat(Wih,Whh) fp16
__device__ float  g_bsum[512];

// ------------------------------------------------------------------ helpers
__device__ __forceinline__ uint32_t smem_u32(const void* p) {
    uint32_t a;
    asm("{ .reg .u64 t; cvta.to.shared.u64 t, %1; cvt.u32.u64 %0, t; }"
        : "=r"(a) : "l"(p));
    return a;
}
__device__ __forceinline__ void ldsm_x4(uint32_t* r, uint32_t addr) {
    asm volatile("ldmatrix.sync.aligned.m8n8.x4.shared.b16 {%0,%1,%2,%3}, [%4];"
                 : "=r"(r[0]), "=r"(r[1]), "=r"(r[2]), "=r"(r[3]) : "r"(addr));
}
__device__ __forceinline__ void mma_f16(float* d, const uint32_t* a, const uint32_t* b) {
    asm volatile("mma.sync.aligned.m16n8k16.row.col.f32.f16.f16.f32 "
                 "{%0,%1,%2,%3}, {%4,%5,%6,%7}, {%8,%9}, {%0,%1,%2,%3};"
                 : "+f"(d[0]), "+f"(d[1]), "+f"(d[2]), "+f"(d[3])
                 : "r"(a[0]), "r"(a[1]), "r"(a[2]), "r"(a[3]), "r"(b[0]), "r"(b[1]));
}
__device__ __forceinline__ void cp_async16(uint32_t saddr, const void* g) {
    asm volatile("cp.async.ca.shared.global [%0], [%1], 16;"
                 :: "r"(saddr), "l"(g) : "memory");
}
__device__ __forceinline__ void cp_async_commit() {
    asm volatile("cp.async.commit_group;" ::: "memory");
}
__device__ __forceinline__ void split2h(float v, __half& hi, __half& lo) {
    hi = __float2half_rn(v);
    lo = __float2half_rn(v - __half2float(hi));
}
__device__ __forceinline__ float sigf(float z) {
    return __fdividef(1.0f, 1.0f + __expf(-z));
}
__device__ __forceinline__ float tanha(float z) {
    return __fdividef(2.0f, 1.0f + __expf(-2.0f * z)) - 1.0f;
}

// ---------------------------------------------------------------- SMEM plan
// Row stride 400B: rows hit distinct bank quads -> conflict-free ldmatrix.
#define RS 400
#define OFF_BIAS 0
#define OFF_AHI  2048
#define OFF_ALO  (OFF_AHI + 64 * RS)    // 27648
#define OFF_B    (OFF_ALO + 64 * RS)    // 53248; two buffers of 25600
#define BUF_SZ   25600
#define SMEM_TC  (OFF_B + 2 * BUF_SZ)   // 104448 -> 2 CTAs/SM (16 warps/SM)

// ---------------------------------------------------------------- prep
__global__ void prep_kernel(const float* __restrict__ Wih,
                            const float* __restrict__ Whh,
                            const float* __restrict__ bih,
                            const float* __restrict__ bhh)
{
    int idx = blockIdx.x * blockDim.x + threadIdx.x;
    if (idx < 512) g_bsum[idx] = bih[idx] + bhh[idx];
    for (int p = idx; p < 512 * 192; p += gridDim.x * blockDim.x) {
        int g = p / 192, k = p - g * 192;
        float v = (k < 64) ? Wih[g * 64 + k] : Whh[g * 128 + (k - 64)];
        g_W[p] = __float2half_rn(v);
    }
}

// =====================================================================
// Tensor-core level kernel: CTA = 64 nodes x 512 gates, 256 threads,
// 8 warps = 4 row-groups (16 nodes) x 2 chunk-halves (4 j-tiles), 2 CTAs/SM.
// fp16 2-term emulation: gates = (Ahi + Alo) * W_fp16, fp32 accum.
// 8 gate-chunks of 64, double-buffered cp.async, one sync per chunk.
// Leaf fast path: h_prev = 0 -> only k 0..63 contribute (dk < 2 of 6).
// Chunk tile j (0..7): gate type j&3, hu octet j>>2. Warp ch owns
// j = 4ch..4ch+3 = full (i,f,g,o) quad -> register-local epilogue.
// B row rr=8j+p -> gate ((j&3)<<7) + nc*16 + ((j>>2)<<3) + p.
// =====================================================================
__global__ __launch_bounds__(256, 2)
void lstm_tc_kernel(const float* __restrict__ x,
                    float* __restrict__ out,
                    int start, int isLeaf)
{
    extern __shared__ __align__(16) char smem[];
    const uint32_t sb = smem_u32(smem);
    const int tid = threadIdx.x;
    const int lane = tid & 31;
    const int rg = (tid >> 5) & 3;     // row group (16 nodes)
    const int ch = tid >> 7;           // chunk half (j-tiles 4ch..4ch+3)
    const int tileBase = blockIdx.x * 64;

    float* bs = (float*)(smem + OFF_BIAS);
    for (int i = tid; i < 512; i += 256) bs[i] = g_bsum[i];

    // ---- A assembly: [64 rows][192 k] fp16 hi/lo ----
    for (int p = tid; p < 2048; p += 256) {        // x part: k 0..63 (convert)
        int row = p >> 5;
        int kp  = (p & 31) * 2;
        int gnode = start + tileBase + row;
        float2 xv = *(const float2*)(x + (size_t)gnode * 64 + kp);
        __half h0, l0, h1, l1;
        split2h(xv.x, h0, l0);
        split2h(xv.y, h1, l1);
        __half2 hp = {h0, h1}, lp = {l0, l1};
        *(uint32_t*)(smem + OFF_AHI + row * RS + kp * 2) = *(uint32_t*)&hp;
        *(uint32_t*)(smem + OFF_ALO + row * RS + kp * 2) = *(uint32_t*)&lp;
    }
    if (!isLeaf) {                                  // h part: k 64..191, cp.async
        for (int p = tid; p < 1024; p += 256) {
            int row = p >> 4;
            int u   = p & 15;                       // 0..7 left, 8..15 right
            int gnode = start + tileBase + row;
            int child = (u < 8) ? (2 * gnode + 1) : (2 * gnode + 2);
            int uu = u & 7;
            uint32_t da = sb + (uint32_t)(row * RS + 128 + u * 16);
            cp_async16(da + OFF_AHI, g_hh + (size_t)child * 64 + uu * 8);
            cp_async16(da + OFF_ALO, g_hl + (size_t)child * 64 + uu * 8);
        }
    }
    // (leaf: k 64..191 never read -- dk loop is bounded to the x columns)

    // ---- B chunk prefetch (64 gates x 192 k fp16) into buf ----
    auto issue_b = [&](int nc, int buf) {
        uint32_t bo = sb + OFF_B + (uint32_t)buf * BUF_SZ;
        #pragma unroll
        for (int it = 0; it < 6; ++it) {
            int p = tid + it * 256;                // p < 1536
            int rr = p / 24, u = p - rr * 24;
            int j = rr >> 3, w = rr & 7;
            int gate = ((j & 3) << 7) + (nc << 4) + ((j >> 2) << 3) + w;
            cp_async16(bo + (uint32_t)(rr * RS + u * 16),
                       g_W + (size_t)gate * 192 + u * 8);
        }
    };

    issue_b(0, 0);          // group 0 = A h-parts + B chunk 0
    cp_async_commit();

    // per-lane ldmatrix bases
    const uint32_t aHi = sb + OFF_AHI +
        (uint32_t)((rg * 16 + (lane & 15)) * RS + ((lane >> 4) << 4));
    const uint32_t aLo = aHi + (OFF_ALO - OFF_AHI);
    // B x4 covers 2 k-steps: lane octet -> k byte-block 0/16/32/48
    const uint32_t bBase = sb + OFF_B +
        (uint32_t)(ch * 32 * RS + (lane & 7) * RS + ((lane >> 3) << 4));
    const int r0   = rg * 16 + (lane >> 2);
    const int huL0 = (lane & 3) * 2;

    for (int nc = 0; nc < 8; ++nc) {
        asm volatile("cp.async.wait_group 0;" ::: "memory");  // buf nc ready
        __syncthreads();   // all warps see buf nc; prior reads of this slot done
        if (nc < 7) {      // prefetch next chunk under this chunk's MMA
            issue_b(nc + 1, (nc + 1) & 1);
            cp_async_commit();
        }

        const uint32_t bHi = bBase + (uint32_t)(nc & 1) * BUF_SZ;

        float acc[4][4];
        #pragma unroll
        for (int j = 0; j < 4; ++j)
            #pragma unroll
            for (int c = 0; c < 4; ++c) acc[j][c] = 0.f;

        auto do_dk = [&](int dk) {
            uint32_t ah0[4], al0[4], ah1[4], al1[4];
            ldsm_x4(ah0, aHi + dk * 64);
            ldsm_x4(al0, aLo + dk * 64);
            ldsm_x4(ah1, aHi + dk * 64 + 32);
            ldsm_x4(al1, aLo + dk * 64 + 32);
            #pragma unroll
            for (int jj = 0; jj < 4; ++jj) {
                uint32_t bh[4];
                ldsm_x4(bh, bHi + jj * (8 * RS) + dk * 64);
                mma_f16(acc[jj], ah0, bh);
                mma_f16(acc[jj], al0, bh);
                mma_f16(acc[jj], ah1, bh + 2);
                mma_f16(acc[jj], al1, bh + 2);
            }
        };
        if (isLeaf) {
            #pragma unroll
            for (int dk = 0; dk < 2; ++dk) do_dk(dk);   // x columns only
        } else {
            #pragma unroll
            for (int dk = 0; dk < 6; ++dk) do_dk(dk);
        }

        // ---- fused LSTM epilogue: this warp owns full (i,f,g,o) quad ----
        const int hu = (nc << 4) + (ch << 3) + huL0;   // even pair {hu, hu+1}
        #pragma unroll
        for (int rh = 0; rh < 2; ++rh) {
            const int row = r0 + 8 * rh;
            const int gnode = start + tileBase + row;
            float2 cp = make_float2(0.f, 0.f);
            if (!isLeaf) {
                int child = (hu < 64) ? (2 * gnode + 1) : (2 * gnode + 2);
                cp = *(const float2*)(g_c + (size_t)child * 64 + (hu & 63));
            }
            float gi0 = acc[0][2 * rh]     + bs[hu];
            float gi1 = acc[0][2 * rh + 1] + bs[hu + 1];
            float gf0 = acc[1][2 * rh]     + bs[128 + hu];
            float gf1 = acc[1][2 * rh + 1] + bs[128 + hu + 1];
            float gg0 = acc[2][2 * rh]     + bs[256 + hu];
            float gg1 = acc[2][2 * rh + 1] + bs[256 + hu + 1];
            float go0 = acc[3][2 * rh]     + bs[384 + hu];
            float go1 = acc[3][2 * rh + 1] + bs[384 + hu + 1];
            float c0 = sigf(gf0) * cp.x + sigf(gi0) * tanha(gg0);
            float c1 = sigf(gf1) * cp.y + sigf(gi1) * tanha(gg1);
            float h0 = sigf(go0) * tanha(c0);
            float h1 = sigf(go1) * tanha(c1);
            *(float2*)(out + (size_t)gnode * 128 + hu) = make_float2(h0, h1);
            if (hu < 64) {
                *(float2*)(g_c + (size_t)gnode * 64 + hu) = make_float2(c0, c1);
                __half hh0, hl0, hh1, hl1;
                split2h(h0, hh0, hl0);
                split2h(h1, hh1, hl1);
                __half2 hp = {hh0, hh1}, lp = {hl0, hl1};
                *(uint32_t*)(g_hh + (size_t)gnode * 64 + hu) = *(uint32_t*)&hp;
                *(uint32_t*)(g_hl + (size_t)gnode * 64 + hu) = *(uint32_t*)&lp;
            }
        }
    }
}

// =====================================================================
// Small-level SIMT kernel: 8 nodes per 256-thread block.
// =====================================================================
__global__ __launch_bounds__(256, 4)
void lstm_small_kernel(const float* __restrict__ x,
                       const float* __restrict__ Wih,
                       const float* __restrict__ Whh,
                       const float* __restrict__ bih,
                       const float* __restrict__ bhh,
                       float* __restrict__ out,
                       int start, int count, int isLeaf)
{
    __shared__ __align__(16) float As[8][196];
    __shared__ __align__(16) float Cs[8][128];
    __shared__ float bsm[512];

    const int t = threadIdx.x;
    const int tileBase = blockIdx.x * 8;

    for (int i = t; i < 512; i += 256) bsm[i] = bih[i] + bhh[i];

    for (int q = t; q < 384; q += 256) {
        int node = q / 48, c4 = q - node * 48, col = c4 * 4;
        float4 v = make_float4(0.f, 0.f, 0.f, 0.f);
        int nodeIdx = tileBase + node;
        if (nodeIdx < count) {
            int gnode = start + nodeIdx;
            if (col < 64) {
                v = *(const float4*)(x + (size_t)gnode * 64 + col);
            } else if (!isLeaf) {
                int child = (col < 128) ? (2 * gnode + 1) : (2 * gnode + 2);
                int cc    = (col < 128) ? (col - 64) : (col - 128);
                v = *(const float4*)(out + (size_t)child * 128 + cc);
            }
        }
        *(float4*)&As[node][col] = v;
    }
    {
        int node = t / 32, col = (t & 31) * 4;
        float4 v = make_float4(0.f, 0.f, 0.f, 0.f);
        int nodeIdx = tileBase + node;
        if (nodeIdx < count && !isLeaf) {
            int gnode = start + nodeIdx;
            int child = (col < 64) ? (2 * gnode + 1) : (2 * gnode + 2);
            int cc    = (col < 64) ? col : (col - 64);
            v = *(const float4*)&g_c[(size_t)child * 64 + cc];
        }
        *(float4*)&Cs[node][col] = v;
    }
    __syncthreads();

    const int hu = t & 127;
    const int np = t >> 7;
    float acc[4][4];
    #pragma unroll
    for (int n = 0; n < 4; ++n)
        #pragma unroll
        for (int g = 0; g < 4; ++g)
            acc[n][g] = bsm[hu + g * 128];

    for (int kc = 0; kc < 48; ++kc) {
        const int k0 = kc * 4;
        float4 w[4];
        #pragma unroll
        for (int g = 0; g < 4; ++g) {
            int grow = hu + g * 128;
            w[g] = (k0 < 64)
                 ? *(const float4*)(Wih + (size_t)grow * 64 + k0)
                 : *(const float4*)(Whh + (size_t)grow * 128 + (k0 - 64));
        }
        #pragma unroll
        for (int n = 0; n < 4; ++n) {
            float4 a = *(const float4*)&As[np + 2 * n][k0];
            #pragma unroll
            for (int g = 0; g < 4; ++g)
                acc[n][g] += a.x * w[g].x + a.y * w[g].y + a.z * w[g].z + a.w * w[g].w;
        }
    }

    #pragma unroll
    for (int n = 0; n < 4; ++n) {
        int nn = np + 2 * n;
        int nodeIdx = tileBase + nn;
        if (nodeIdx < count) {
            int gnode = start + nodeIdx;
            float cp = Cs[nn][hu];
            float c = sigf(acc[n][1]) * cp + sigf(acc[n][0]) * tanha(acc[n][2]);
            float h = sigf(acc[n][3]) * tanha(c);
            out[(size_t)gnode * 128 + hu] = h;
            if (hu < 64) g_c[(size_t)gnode * 64 + hu] = c;
        }
    }
}

extern "C" void kernel_launch(void* const* d_in, const int* in_sizes, int n_in,
                              void* d_out, int out_size)
{
    const float* x   = (const float*)d_in[0];   // [262143, 64]
    const float* Wih = (const float*)d_in[1];   // [512, 64]
    const float* Whh = (const float*)d_in[2];   // [512, 128]
    const float* bih = (const float*)d_in[3];   // [512]
    const float* bhh = (const float*)d_in[4];   // [512]
    float* out = (float*)d_out;                 // [262143, 128]

    static bool attr_done = false;
    if (!attr_done) {
        cudaFuncSetAttribute(lstm_tc_kernel,
                             cudaFuncAttributeMaxDynamicSharedMemorySize, SMEM_TC);
        attr_done = true;
    }

    prep_kernel<<<96, 256>>>(Wih, Whh, bih, bhh);

    for (int lvl = LEVELS - 1; lvl >= 0; --lvl) {
        int start = (1 << lvl) - 1;
        int count = 1 << lvl;
        int isLeaf = (lvl == LEVELS - 1);
        if (count >= 1024) {
            lstm_tc_kernel<<<count / 64, 256, SMEM_TC>>>(x, out, start, isLeaf);
        } else {
            lstm_small_kernel<<<(count + 7) / 8, 256>>>(
                x, Wih, Whh, bih, bhh, out, start, count, isLeaf);
        }
    }
}

// round 10
// speedup vs baseline: 1.7575x; 1.1437x over previous
#include <cuda_runtime.h>
#include <cuda_fp16.h>
#include <cstdint>

#define LEVELS 18
#define NNODES ((1 << LEVELS) - 1)

// Persisted state + preconverted weights (device globals; no runtime alloc).
__device__ float  g_c [(size_t)NNODES * 64];   // cell state, cols 0..63 only
__device__ __half g_hh[(size_t)NNODES * 64];   // h fp16, cols 0..63
__device__ __half g_W [512 * 192];             // [gate][k] concat(Wih,Whh) fp16
__device__ float  g_bsum[512];

// ------------------------------------------------------------------ helpers
__device__ __forceinline__ uint32_t smem_u32(const void* p) {
    uint32_t a;
    asm("{ .reg .u64 t; cvta.to.shared.u64 t, %1; cvt.u32.u64 %0, t; }"
        : "=r"(a) : "l"(p));
    return a;
}
__device__ __forceinline__ void ldsm_x4(uint32_t* r, uint32_t addr) {
    asm volatile("ldmatrix.sync.aligned.m8n8.x4.shared.b16 {%0,%1,%2,%3}, [%4];"
                 : "=r"(r[0]), "=r"(r[1]), "=r"(r[2]), "=r"(r[3]) : "r"(addr));
}
__device__ __forceinline__ void mma_f16(float* d, const uint32_t* a, const uint32_t* b) {
    asm volatile("mma.sync.aligned.m16n8k16.row.col.f32.f16.f16.f32 "
                 "{%0,%1,%2,%3}, {%4,%5,%6,%7}, {%8,%9}, {%0,%1,%2,%3};"
                 : "+f"(d[0]), "+f"(d[1]), "+f"(d[2]), "+f"(d[3])
                 : "r"(a[0]), "r"(a[1]), "r"(a[2]), "r"(a[3]), "r"(b[0]), "r"(b[1]));
}
__device__ __forceinline__ void cp_async16(uint32_t saddr, const void* g) {
    asm volatile("cp.async.ca.shared.global [%0], [%1], 16;"
                 :: "r"(saddr), "l"(g) : "memory");
}
__device__ __forceinline__ void cp_async_commit() {
    asm volatile("cp.async.commit_group;" ::: "memory");
}
__device__ __forceinline__ float sigf(float z) {
    return __fdividef(1.0f, 1.0f + __expf(-z));
}
__device__ __forceinline__ float tanha(float z) {
    return __fdividef(2.0f, 1.0f + __expf(-2.0f * z)) - 1.0f;
}

// ---------------------------------------------------------------- SMEM plan
// Row stride 400B: rows hit distinct bank quads -> conflict-free ldmatrix.
#define RS 400
#define OFF_BIAS 0
#define OFF_A    2048
#define OFF_B    (OFF_A + 64 * RS)      // 27648; two buffers of 25600
#define BUF_SZ   25600
#define SMEM_TC  (OFF_B + 2 * BUF_SZ)   // 78848 -> 2 CTAs/SM (16 warps/SM)

// ---------------------------------------------------------------- prep
__global__ void prep_kernel(const float* __restrict__ Wih,
                            const float* __restrict__ Whh,
                            const float* __restrict__ bih,
                            const float* __restrict__ bhh)
{
    int idx = blockIdx.x * blockDim.x + threadIdx.x;
    if (idx < 512) g_bsum[idx] = bih[idx] + bhh[idx];
    for (int p = idx; p < 512 * 192; p += gridDim.x * blockDim.x) {
        int g = p / 192, k = p - g * 192;
        float v = (k < 64) ? Wih[g * 64 + k] : Whh[g * 128 + (k - 64)];
        g_W[p] = __float2half_rn(v);
    }
}

// =====================================================================
// Tensor-core level kernel: CTA = 64 nodes x (512/gs) gates, 256 threads,
// 8 warps = 4 row-groups (16 nodes) x 2 chunk-halves, 2 CTAs/SM.
// Single-term fp16: gates = A_fp16 * W_fp16, fp32 accum.
// Gate-chunks of 64 are independent; CTA handles cpc = 8/gs of them
// (gate-split over blockIdx for under-filled levels).
// Leaf fast path: h_prev = 0 -> only k 0..63 contribute (dk < 2 of 6).
// Chunk tile j (0..7): gate type j&3, hu octet j>>2. Warp ch owns
// j = 4ch..4ch+3 = full (i,f,g,o) quad -> register-local epilogue.
// B row rr=8j+p -> gate ((j&3)<<7) + nc*16 + ((j>>2)<<3) + p.
// =====================================================================
__global__ __launch_bounds__(256, 2)
void lstm_tc_kernel(const float* __restrict__ x,
                    float* __restrict__ out,
                    int start, int isLeaf, int tiles, int cpc)
{
    extern __shared__ __align__(16) char smem[];
    const uint32_t sb = smem_u32(smem);
    const int tid = threadIdx.x;
    const int lane = tid & 31;
    const int rg = (tid >> 5) & 3;     // row group (16 nodes)
    const int ch = tid >> 7;           // chunk half (j-tiles 4ch..4ch+3)
    const int tile  = blockIdx.x % tiles;
    const int nc0   = (blockIdx.x / tiles) * cpc;   // first gate-chunk
    const int tileBase = tile * 64;

    float* bs = (float*)(smem + OFF_BIAS);
    for (int i = tid; i < 512; i += 256) bs[i] = g_bsum[i];

    // ---- A assembly: [64 rows][192 k] fp16 ----
    for (int p = tid; p < 2048; p += 256) {        // x part: k 0..63 (convert)
        int row = p >> 5;
        int kp  = (p & 31) * 2;
        int gnode = start + tileBase + row;
        float2 xv = *(const float2*)(x + (size_t)gnode * 64 + kp);
        __half2 hp = {__float2half_rn(xv.x), __float2half_rn(xv.y)};
        *(uint32_t*)(smem + OFF_A + row * RS + kp * 2) = *(uint32_t*)&hp;
    }
    if (!isLeaf) {                                  // h part: k 64..191, cp.async
        for (int p = tid; p < 1024; p += 256) {
            int row = p >> 4;
            int u   = p & 15;                       // 0..7 left, 8..15 right
            int gnode = start + tileBase + row;
            int child = (u < 8) ? (2 * gnode + 1) : (2 * gnode + 2);
            int uu = u & 7;
            cp_async16(sb + OFF_A + (uint32_t)(row * RS + 128 + u * 16),
                       g_hh + (size_t)child * 64 + uu * 8);
        }
    }
    // (leaf: k 64..191 never read -- dk loop is bounded to the x columns)

    // ---- B chunk prefetch (64 gates x 192 k fp16) into buf ----
    auto issue_b = [&](int nc, int buf) {
        uint32_t bo = sb + OFF_B + (uint32_t)buf * BUF_SZ;
        #pragma unroll
        for (int it = 0; it < 6; ++it) {
            int p = tid + it * 256;                // p < 1536
            int rr = p / 24, u = p - rr * 24;
            int j = rr >> 3, w = rr & 7;
            int gate = ((j & 3) << 7) + (nc << 4) + ((j >> 2) << 3) + w;
            cp_async16(bo + (uint32_t)(rr * RS + u * 16),
                       g_W + (size_t)gate * 192 + u * 8);
        }
    };

    issue_b(nc0, 0);        // group 0 = A h-parts + B chunk nc0
    cp_async_commit();

    // per-lane ldmatrix bases
    const uint32_t aBase = sb + OFF_A +
        (uint32_t)((rg * 16 + (lane & 15)) * RS + ((lane >> 4) << 4));
    // B x4 covers 2 k-steps: lane octet -> k byte-block 0/16/32/48
    const uint32_t bBase = sb + OFF_B +
        (uint32_t)(ch * 32 * RS + (lane & 7) * RS + ((lane >> 3) << 4));
    const int r0   = rg * 16 + (lane >> 2);
    const int huL0 = (lane & 3) * 2;

    for (int l = 0; l < cpc; ++l) {
        const int nc = nc0 + l;
        asm volatile("cp.async.wait_group 0;" ::: "memory");  // buf l ready
        __syncthreads();   // all warps see buf l; prior reads of this slot done
        if (l + 1 < cpc) { // prefetch next chunk under this chunk's MMA
            issue_b(nc + 1, (l + 1) & 1);
            cp_async_commit();
        }

        const uint32_t bHi = bBase + (uint32_t)(l & 1) * BUF_SZ;

        float acc[4][4];
        #pragma unroll
        for (int j = 0; j < 4; ++j)
            #pragma unroll
            for (int c = 0; c < 4; ++c) acc[j][c] = 0.f;

        auto do_dk = [&](int dk) {
            uint32_t a0[4], a1[4];
            ldsm_x4(a0, aBase + dk * 64);
            ldsm_x4(a1, aBase + dk * 64 + 32);
            #pragma unroll
            for (int jj = 0; jj < 4; ++jj) {
                uint32_t bh[4];
                ldsm_x4(bh, bHi + jj * (8 * RS) + dk * 64);
                mma_f16(acc[jj], a0, bh);
                mma_f16(acc[jj], a1, bh + 2);
            }
        };
        if (isLeaf) {
            #pragma unroll
            for (int dk = 0; dk < 2; ++dk) do_dk(dk);   // x columns only
        } else {
            #pragma unroll
            for (int dk = 0; dk < 6; ++dk) do_dk(dk);
        }

        // ---- fused LSTM epilogue: this warp owns full (i,f,g,o) quad ----
        const int hu = (nc << 4) + (ch << 3) + huL0;   // even pair {hu, hu+1}
        #pragma unroll
        for (int rh = 0; rh < 2; ++rh) {
            const int row = r0 + 8 * rh;
            const int gnode = start + tileBase + row;
            float2 cp = make_float2(0.f, 0.f);
            if (!isLeaf) {
                int child = (hu < 64) ? (2 * gnode + 1) : (2 * gnode + 2);
                cp = *(const float2*)(g_c + (size_t)child * 64 + (hu & 63));
            }
            float gi0 = acc[0][2 * rh]     + bs[hu];
            float gi1 = acc[0][2 * rh + 1] + bs[hu + 1];
            float gf0 = acc[1][2 * rh]     + bs[128 + hu];
            float gf1 = acc[1][2 * rh + 1] + bs[128 + hu + 1];
            float gg0 = acc[2][2 * rh]     + bs[256 + hu];
            float gg1 = acc[2][2 * rh + 1] + bs[256 + hu + 1];
            float go0 = acc[3][2 * rh]     + bs[384 + hu];
            float go1 = acc[3][2 * rh + 1] + bs[384 + hu + 1];
            float c0 = sigf(gf0) * cp.x + sigf(gi0) * tanha(gg0);
            float c1 = sigf(gf1) * cp.y + sigf(gi1) * tanha(gg1);
            float h0 = sigf(go0) * tanha(c0);
            float h1 = sigf(go1) * tanha(c1);
            *(float2*)(out + (size_t)gnode * 128 + hu) = make_float2(h0, h1);
            if (hu < 64) {
                *(float2*)(g_c + (size_t)gnode * 64 + hu) = make_float2(c0, c1);
                __half2 hp = {__float2half_rn(h0), __float2half_rn(h1)};
                *(uint32_t*)(g_hh + (size_t)gnode * 64 + hu) = *(uint32_t*)&hp;
            }
        }
    }
}

// =====================================================================
// Small-level SIMT kernel: 8 nodes per 256-thread block.
// =====================================================================
__global__ __launch_bounds__(256, 4)
void lstm_small_kernel(const float* __restrict__ x,
                       const float* __restrict__ Wih,
                       const float* __restrict__ Whh,
                       const float* __restrict__ bih,
                       const float* __restrict__ bhh,
                       float* __restrict__ out,
                       int start, int count, int isLeaf)
{
    __shared__ __align__(16) float As[8][196];
    __shared__ __align__(16) float Cs[8][128];
    __shared__ float bsm[512];

    const int t = threadIdx.x;
    const int tileBase = blockIdx.x * 8;

    for (int i = t; i < 512; i += 256) bsm[i] = bih[i] + bhh[i];

    for (int q = t; q < 384; q += 256) {
        int node = q / 48, c4 = q - node * 48, col = c4 * 4;
        float4 v = make_float4(0.f, 0.f, 0.f, 0.f);
        int nodeIdx = tileBase + node;
        if (nodeIdx < count) {
            int gnode = start + nodeIdx;
            if (col < 64) {
                v = *(const float4*)(x + (size_t)gnode * 64 + col);
            } else if (!isLeaf) {
                int child = (col < 128) ? (2 * gnode + 1) : (2 * gnode + 2);
                int cc    = (col < 128) ? (col - 64) : (col - 128);
                v = *(const float4*)(out + (size_t)child * 128 + cc);
            }
        }
        *(float4*)&As[node][col] = v;
    }
    {
        int node = t / 32, col = (t & 31) * 4;
        float4 v = make_float4(0.f, 0.f, 0.f, 0.f);
        int nodeIdx = tileBase + node;
        if (nodeIdx < count && !isLeaf) {
            int gnode = start + nodeIdx;
            int child = (col < 64) ? (2 * gnode + 1) : (2 * gnode + 2);
            int cc    = (col < 64) ? col : (col - 64);
            v = *(const float4*)&g_c[(size_t)child * 64 + cc];
        }
        *(float4*)&Cs[node][col] = v;
    }
    __syncthreads();

    const int hu = t & 127;
    const int np = t >> 7;
    float acc[4][4];
    #pragma unroll
    for (int n = 0; n < 4; ++n)
        #pragma unroll
        for (int g = 0; g < 4; ++g)
            acc[n][g] = bsm[hu + g * 128];

    for (int kc = 0; kc < 48; ++kc) {
        const int k0 = kc * 4;
        float4 w[4];
        #pragma unroll
        for (int g = 0; g < 4; ++g) {
            int grow = hu + g * 128;
            w[g] = (k0 < 64)
                 ? *(const float4*)(Wih + (size_t)grow * 64 + k0)
                 : *(const float4*)(Whh + (size_t)grow * 128 + (k0 - 64));
        }
        #pragma unroll
        for (int n = 0; n < 4; ++n) {
            float4 a = *(const float4*)&As[np + 2 * n][k0];
            #pragma unroll
            for (int g = 0; g < 4; ++g)
                acc[n][g] += a.x * w[g].x + a.y * w[g].y + a.z * w[g].z + a.w * w[g].w;
        }
    }

    #pragma unroll
    for (int n = 0; n < 4; ++n) {
        int nn = np + 2 * n;
        int nodeIdx = tileBase + nn;
        if (nodeIdx < count) {
            int gnode = start + nodeIdx;
            float cp = Cs[nn][hu];
            float c = sigf(acc[n][1]) * cp + sigf(acc[n][0]) * tanha(acc[n][2]);
            float h = sigf(acc[n][3]) * tanha(c);
            out[(size_t)gnode * 128 + hu] = h;
            if (hu < 64) g_c[(size_t)gnode * 64 + hu] = c;
        }
    }
}

extern "C" void kernel_launch(void* const* d_in, const int* in_sizes, int n_in,
                              void* d_out, int out_size)
{
    const float* x   = (const float*)d_in[0];   // [262143, 64]
    const float* Wih = (const float*)d_in[1];   // [512, 64]
    const float* Whh = (const float*)d_in[2];   // [512, 128]
    const float* bih = (const float*)d_in[3];   // [512]
    const float* bhh = (const float*)d_in[4];   // [512]
    float* out = (float*)d_out;                 // [262143, 128]

    static bool attr_done = false;
    if (!attr_done) {
        cudaFuncSetAttribute(lstm_tc_kernel,
                             cudaFuncAttributeMaxDynamicSharedMemorySize, SMEM_TC);
        attr_done = true;
    }

    prep_kernel<<<96, 256>>>(Wih, Whh, bih, bhh);

    const int CONC = 296;   // 148 SMs x 2 CTAs
    for (int lvl = LEVELS - 1; lvl >= 0; --lvl) {
        int start = (1 << lvl) - 1;
        int count = 1 << lvl;
        int isLeaf = (lvl == LEVELS - 1);
        if (count >= 1024) {
            int tiles = count / 64;
            int gs = 1;
            while (gs < 8 && tiles * gs * 2 <= CONC) gs <<= 1;  // fill, stay 1 wave
            lstm_tc_kernel<<<tiles * gs, 256, SMEM_TC>>>(
                x, out, start, isLeaf, tiles, 8 / gs);
        } else {
            lstm_small_kernel<<<(count + 7) / 8, 256>>>(
                x, Wih, Whh, bih, bhh, out, start, count, isLeaf);
        }
    }
}

// round 11
// speedup vs baseline: 2.1041x; 1.1972x over previous
#include <cuda_runtime.h>
#include <cuda_fp16.h>
#include <cstdint>

#define LEVELS 18
#define NNODES ((1 << LEVELS) - 1)

// Persisted state + preconverted weights (device globals; no runtime alloc).
__device__ float  g_c [(size_t)NNODES * 64];   // cell state, cols 0..63 only
__device__ __half g_hh[(size_t)NNODES * 64];   // h fp16, cols 0..63
__device__ __half g_W [512 * 192];             // [gate][k] concat(Wih,Whh) fp16
__device__ float  g_bsum[512];

// ------------------------------------------------------------------ helpers
__device__ __forceinline__ uint32_t smem_u32(const void* p) {
    uint32_t a;
    asm("{ .reg .u64 t; cvta.to.shared.u64 t, %1; cvt.u32.u64 %0, t; }"
        : "=r"(a) : "l"(p));
    return a;
}
__device__ __forceinline__ void ldsm_x4(uint32_t* r, uint32_t addr) {
    asm volatile("ldmatrix.sync.aligned.m8n8.x4.shared.b16 {%0,%1,%2,%3}, [%4];"
                 : "=r"(r[0]), "=r"(r[1]), "=r"(r[2]), "=r"(r[3]) : "r"(addr));
}
__device__ __forceinline__ void mma_f16(float* d, const uint32_t* a, const uint32_t* b) {
    asm volatile("mma.sync.aligned.m16n8k16.row.col.f32.f16.f16.f32 "
                 "{%0,%1,%2,%3}, {%4,%5,%6,%7}, {%8,%9}, {%0,%1,%2,%3};"
                 : "+f"(d[0]), "+f"(d[1]), "+f"(d[2]), "+f"(d[3])
                 : "r"(a[0]), "r"(a[1]), "r"(a[2]), "r"(a[3]), "r"(b[0]), "r"(b[1]));
}
__device__ __forceinline__ void cp_async16(uint32_t saddr, const void* g) {
    asm volatile("cp.async.ca.shared.global [%0], [%1], 16;"
                 :: "r"(saddr), "l"(g) : "memory");
}
__device__ __forceinline__ void cp_async_commit() {
    asm volatile("cp.async.commit_group;" ::: "memory");
}
__device__ __forceinline__ float tanhfast(float z) {
    float r;
    asm("tanh.approx.f32 %0, %1;" : "=f"(r) : "f"(z));
    return r;
}
__device__ __forceinline__ float sigf(float z) {
    return fmaf(tanhfast(0.5f * z), 0.5f, 0.5f);
}

// ---------------------------------------------------------------- SMEM plan
// Row stride 400B: rows hit distinct bank quads -> conflict-free ldmatrix.
#define RS 400
#define OFF_BIAS 0
#define OFF_A    2048
#define OFF_B    (OFF_A + 128 * RS)     // 53248; two buffers of 25600
#define BUF_SZ   25600
#define SMEM_TC  (OFF_B + 2 * BUF_SZ)   // 104448 -> 2 CTAs/SM (16 warps/SM)

// ---------------------------------------------------------------- prep
__global__ void prep_kernel(const float* __restrict__ Wih,
                            const float* __restrict__ Whh,
                            const float* __restrict__ bih,
                            const float* __restrict__ bhh)
{
    int idx = blockIdx.x * blockDim.x + threadIdx.x;
    if (idx < 512) g_bsum[idx] = bih[idx] + bhh[idx];
    for (int p = idx; p < 512 * 192; p += gridDim.x * blockDim.x) {
        int g = p / 192, k = p - g * 192;
        float v = (k < 64) ? Wih[g * 64 + k] : Whh[g * 128 + (k - 64)];
        g_W[p] = __float2half_rn(v);
    }
}

// =====================================================================
// Tensor-core level kernel: CTA = 128 nodes x (512/gs) gates, 256 threads,
// 8 warps = 4 row-groups (32 nodes) x 2 chunk-halves, 2 CTAs/SM.
// Warp tile M=32 (2 m16 tiles) x N=32 (4 j-tiles) -> LDSM:MMA = 1:2.
// Single-term fp16: gates = A_fp16 * W_fp16, fp32 accum.
// Gate-chunks of 64 are independent; CTA handles cpc = 8/gs of them.
// Leaf fast path: h_prev = 0 -> only k 0..63 (dk<2) AND B rows k<64 loaded.
// Chunk tile j = 4ch+jj: gate type jj, hu octet ch. Warp ch owns a full
// (i,f,g,o) quad of one hu octet -> register-local epilogue.
// B row rr=8j+p -> gate (jj<<7) + nc*16 + (ch<<3) + p.
// =====================================================================
__global__ __launch_bounds__(256, 2)
void lstm_tc_kernel(const float* __restrict__ x,
                    float* __restrict__ out,
                    int start, int isLeaf, int tiles, int cpc)
{
    extern __shared__ __align__(16) char smem[];
    const uint32_t sb = smem_u32(smem);
    const int tid = threadIdx.x;
    const int lane = tid & 31;
    const int rg = (tid >> 5) & 3;     // row group (32 nodes)
    const int ch = tid >> 7;           // chunk half (j-tiles 4ch..4ch+3)
    const int tile  = blockIdx.x % tiles;
    const int nc0   = (blockIdx.x / tiles) * cpc;   // first gate-chunk
    const int tileBase = tile * 128;

    float* bs = (float*)(smem + OFF_BIAS);
    for (int i = tid; i < 512; i += 256) bs[i] = g_bsum[i];

    // ---- A assembly: [128 rows][192 k] fp16 ----
    #pragma unroll
    for (int it = 0; it < 16; ++it) {              // x part: k 0..63 (convert)
        int p = tid + it * 256;
        int row = p >> 5;
        int kp  = (p & 31) * 2;
        int gnode = start + tileBase + row;
        float2 xv = *(const float2*)(x + (size_t)gnode * 64 + kp);
        __half2 hp = {__float2half_rn(xv.x), __float2half_rn(xv.y)};
        *(uint32_t*)(smem + OFF_A + row * RS + kp * 2) = *(uint32_t*)&hp;
    }
    if (!isLeaf) {                                  // h part: k 64..191, cp.async
        #pragma unroll
        for (int it = 0; it < 8; ++it) {
            int p = tid + it * 256;
            int row = p >> 4;
            int u   = p & 15;                       // 0..7 left, 8..15 right
            int gnode = start + tileBase + row;
            int child = (u < 8) ? (2 * gnode + 1) : (2 * gnode + 2);
            int uu = u & 7;
            cp_async16(sb + OFF_A + (uint32_t)(row * RS + 128 + u * 16),
                       g_hh + (size_t)child * 64 + uu * 8);
        }
    }
    // (leaf: k 64..191 never read -- dk loop and B loads bounded to x columns)

    // ---- B chunk prefetch into buf: rowsU uint4 per row (24 full, 8 leaf)
    auto issue_b = [&](int nc, int buf) {
        uint32_t bo = sb + OFF_B + (uint32_t)buf * BUF_SZ;
        if (isLeaf) {
            #pragma unroll
            for (int it = 0; it < 2; ++it) {
                int p = tid + it * 256;            // p < 512: 64 rows x 8 uint4
                int rr = p >> 3, u = p & 7;
                int j = rr >> 3, w = rr & 7;
                int gate = ((j & 3) << 7) + (nc << 4) + ((j >> 2) << 3) + w;
                cp_async16(bo + (uint32_t)(rr * RS + u * 16),
                           g_W + (size_t)gate * 192 + u * 8);
            }
        } else {
            #pragma unroll
            for (int it = 0; it < 6; ++it) {
                int p = tid + it * 256;            // p < 1536: 64 rows x 24
                int rr = p / 24, u = p - rr * 24;
                int j = rr >> 3, w = rr & 7;
                int gate = ((j & 3) << 7) + (nc << 4) + ((j >> 2) << 3) + w;
                cp_async16(bo + (uint32_t)(rr * RS + u * 16),
                           g_W + (size_t)gate * 192 + u * 8);
            }
        }
    };

    issue_b(nc0, 0);        // group 0 = A h-parts + B chunk nc0
    cp_async_commit();

    // per-lane ldmatrix bases
    const uint32_t aBase = sb + OFF_A +
        (uint32_t)((rg * 32 + (lane & 15)) * RS + ((lane >> 4) << 4));
    // B x4 covers 2 k-steps: lane octet -> k byte-block 0/16/32/48
    const uint32_t bBase = sb + OFF_B +
        (uint32_t)(ch * 32 * RS + (lane & 7) * RS + ((lane >> 3) << 4));
    const int r0   = rg * 32 + (lane >> 2);
    const int huL0 = (lane & 3) * 2;

    for (int l = 0; l < cpc; ++l) {
        const int nc = nc0 + l;
        asm volatile("cp.async.wait_group 0;" ::: "memory");  // buf l ready
        __syncthreads();   // all warps see buf l; prior reads of this slot done
        if (l + 1 < cpc) { // prefetch next chunk under this chunk's MMA
            issue_b(nc + 1, (l + 1) & 1);
            cp_async_commit();
        }

        const uint32_t bHi = bBase + (uint32_t)(l & 1) * BUF_SZ;

        float acc[2][4][4];
        #pragma unroll
        for (int m = 0; m < 2; ++m)
            #pragma unroll
            for (int j = 0; j < 4; ++j)
                #pragma unroll
                for (int c = 0; c < 4; ++c) acc[m][j][c] = 0.f;

        auto do_dk = [&](int dk) {
            uint32_t a0[2][4], a1[2][4];
            #pragma unroll
            for (int m = 0; m < 2; ++m) {
                ldsm_x4(a0[m], aBase + m * (16 * RS) + dk * 64);
                ldsm_x4(a1[m], aBase + m * (16 * RS) + dk * 64 + 32);
            }
            #pragma unroll
            for (int jj = 0; jj < 4; ++jj) {
                uint32_t bh[4];
                ldsm_x4(bh, bHi + jj * (8 * RS) + dk * 64);
                #pragma unroll
                for (int m = 0; m < 2; ++m) {
                    mma_f16(acc[m][jj], a0[m], bh);
                    mma_f16(acc[m][jj], a1[m], bh + 2);
                }
            }
        };
        if (isLeaf) {
            #pragma unroll
            for (int dk = 0; dk < 2; ++dk) do_dk(dk);   // x columns only
        } else {
            #pragma unroll
            for (int dk = 0; dk < 6; ++dk) do_dk(dk);
        }

        // ---- fused LSTM epilogue: this warp owns full (i,f,g,o) quad ----
        const int hu = (nc << 4) + (ch << 3) + huL0;   // even pair {hu, hu+1}
        #pragma unroll
        for (int m = 0; m < 2; ++m) {
            #pragma unroll
            for (int rh = 0; rh < 2; ++rh) {
                const int row = r0 + m * 16 + 8 * rh;
                const int gnode = start + tileBase + row;
                float2 cp = make_float2(0.f, 0.f);
                if (!isLeaf) {
                    int child = (hu < 64) ? (2 * gnode + 1) : (2 * gnode + 2);
                    cp = *(const float2*)(g_c + (size_t)child * 64 + (hu & 63));
                }
                float gi0 = acc[m][0][2 * rh]     + bs[hu];
                float gi1 = acc[m][0][2 * rh + 1] + bs[hu + 1];
                float gf0 = acc[m][1][2 * rh]     + bs[128 + hu];
                float gf1 = acc[m][1][2 * rh + 1] + bs[128 + hu + 1];
                float gg0 = acc[m][2][2 * rh]     + bs[256 + hu];
                float gg1 = acc[m][2][2 * rh + 1] + bs[256 + hu + 1];
                float go0 = acc[m][3][2 * rh]     + bs[384 + hu];
                float go1 = acc[m][3][2 * rh + 1] + bs[384 + hu + 1];
                float c0 = sigf(gf0) * cp.x + sigf(gi0) * tanhfast(gg0);
                float c1 = sigf(gf1) * cp.y + sigf(gi1) * tanhfast(gg1);
                float h0 = sigf(go0) * tanhfast(c0);
                float h1 = sigf(go1) * tanhfast(c1);
                *(float2*)(out + (size_t)gnode * 128 + hu) = make_float2(h0, h1);
                if (hu < 64) {
                    *(float2*)(g_c + (size_t)gnode * 64 + hu) = make_float2(c0, c1);
                    __half2 hp = {__float2half_rn(h0), __float2half_rn(h1)};
                    *(uint32_t*)(g_hh + (size_t)gnode * 64 + hu) = *(uint32_t*)&hp;
                }
            }
        }
    }
}

// =====================================================================
// Small-level SIMT kernel: 8 nodes per 256-thread block.
// =====================================================================
__global__ __launch_bounds__(256, 4)
void lstm_small_kernel(const float* __restrict__ x,
                       const float* __restrict__ Wih,
                       const float* __restrict__ Whh,
                       const float* __restrict__ bih,
                       const float* __restrict__ bhh,
                       float* __restrict__ out,
                       int start, int count, int isLeaf)
{
    __shared__ __align__(16) float As[8][196];
    __shared__ __align__(16) float Cs[8][128];
    __shared__ float bsm[512];

    const int t = threadIdx.x;
    const int tileBase = blockIdx.x * 8;

    for (int i = t; i < 512; i += 256) bsm[i] = bih[i] + bhh[i];

    for (int q = t; q < 384; q += 256) {
        int node = q / 48, c4 = q - node * 48, col = c4 * 4;
        float4 v = make_float4(0.f, 0.f, 0.f, 0.f);
        int nodeIdx = tileBase + node;
        if (nodeIdx < count) {
            int gnode = start + nodeIdx;
            if (col < 64) {
                v = *(const float4*)(x + (size_t)gnode * 64 + col);
            } else if (!isLeaf) {
                int child = (col < 128) ? (2 * gnode + 1) : (2 * gnode + 2);
                int cc    = (col < 128) ? (col - 64) : (col - 128);
                v = *(const float4*)(out + (size_t)child * 128 + cc);
            }
        }
        *(float4*)&As[node][col] = v;
    }
    {
        int node = t / 32, col = (t & 31) * 4;
        float4 v = make_float4(0.f, 0.f, 0.f, 0.f);
        int nodeIdx = tileBase + node;
        if (nodeIdx < count && !isLeaf) {
            int gnode = start + nodeIdx;
            int child = (col < 64) ? (2 * gnode + 1) : (2 * gnode + 2);
            int cc    = (col < 64) ? col : (col - 64);
            v = *(const float4*)&g_c[(size_t)child * 64 + cc];
        }
        *(float4*)&Cs[node][col] = v;
    }
    __syncthreads();

    const int hu = t & 127;
    const int np = t >> 7;
    float acc[4][4];
    #pragma unroll
    for (int n = 0; n < 4; ++n)
        #pragma unroll
        for (int g = 0; g < 4; ++g)
            acc[n][g] = bsm[hu + g * 128];

    for (int kc = 0; kc < 48; ++kc) {
        const int k0 = kc * 4;
        float4 w[4];
        #pragma unroll
        for (int g = 0; g < 4; ++g) {
            int grow = hu + g * 128;
            w[g] = (k0 < 64)
                 ? *(const float4*)(Wih + (size_t)grow * 64 + k0)
                 : *(const float4*)(Whh + (size_t)grow * 128 + (k0 - 64));
        }
        #pragma unroll
        for (int n = 0; n < 4; ++n) {
            float4 a = *(const float4*)&As[np + 2 * n][k0];
            #pragma unroll
            for (int g = 0; g < 4; ++g)
                acc[n][g] += a.x * w[g].x + a.y * w[g].y + a.z * w[g].z + a.w * w[g].w;
        }
    }

    #pragma unroll
    for (int n = 0; n < 4; ++n) {
        int nn = np + 2 * n;
        int nodeIdx = tileBase + nn;
        if (nodeIdx < count) {
            int gnode = start + nodeIdx;
            float cp = Cs[nn][hu];
            float c = sigf(acc[n][1]) * cp + sigf(acc[n][0]) * tanhfast(acc[n][2]);
            float h = sigf(acc[n][3]) * tanhfast(c);
            out[(size_t)gnode * 128 + hu] = h;
            if (hu < 64) g_c[(size_t)gnode * 64 + hu] = c;
        }
    }
}

extern "C" void kernel_launch(void* const* d_in, const int* in_sizes, int n_in,
                              void* d_out, int out_size)
{
    const float* x   = (const float*)d_in[0];   // [262143, 64]
    const float* Wih = (const float*)d_in[1];   // [512, 64]
    const float* Whh = (const float*)d_in[2];   // [512, 128]
    const float* bih = (const float*)d_in[3];   // [512]
    const float* bhh = (const float*)d_in[4];   // [512]
    float* out = (float*)d_out;                 // [262143, 128]

    static bool attr_done = false;
    if (!attr_done) {
        cudaFuncSetAttribute(lstm_tc_kernel,
                             cudaFuncAttributeMaxDynamicSharedMemorySize, SMEM_TC);
        attr_done = true;
    }

    prep_kernel<<<96, 256>>>(Wih, Whh, bih, bhh);

    const int CONC = 296;   // 148 SMs x 2 CTAs
    for (int lvl = LEVELS - 1; lvl >= 0; --lvl) {
        int start = (1 << lvl) - 1;
        int count = 1 << lvl;
        int isLeaf = (lvl == LEVELS - 1);
        if (count >= 1024) {
            int tiles = count / 128;
            int gs = 1;
            while (gs < 8 && tiles * gs * 2 <= CONC) gs <<= 1;  // fill, stay 1 wave
            lstm_tc_kernel<<<tiles * gs, 256, SMEM_TC>>>(
                x, out, start, isLeaf, tiles, 8 / gs);
        } else {
            lstm_small_kernel<<<(count + 7) / 8, 256>>>(
                x, Wih, Whh, bih, bhh, out, start, count, isLeaf);
        }
    }
}